// round 1
// baseline (speedup 1.0000x reference)
#include <cuda_runtime.h>
#include <cuda_bf16.h>

#define NN   50000
#define EE   800000
#define ET   (EE + NN)        // edges incl. self loops = 850000
#define FD   128
#define HH   2
#define CC   64
#define GG   64
#define OUTD 10

// ---------------- scratch (device globals; no allocation allowed) ----------
__device__ float g_xs [NN * FD];     // source projection
__device__ float g_xd [NN * FD];     // dest projection
__device__ float g_as [NN * HH];     // per-node source attention logit
__device__ float g_ad [NN * HH];     // per-node dest attention logit
__device__ float g_e  [ET * HH];     // per-edge logits / weights
__device__ float g_m  [NN * HH];     // segment max
__device__ float g_den[NN * HH];     // segment sum
__device__ float g_agg[NN * FD];     // aggregated messages
__device__ float g_h  [NN * FD];     // layer output
__device__ float g_pool[GG * FD];
__device__ float g_cnt [GG];

// ---------------- helpers ---------------------------------------------------
__device__ __forceinline__ void atomicMaxF(float* addr, float v) {
    // float ordering == signed int ordering for >=0, reversed unsigned for <0
    if (v >= 0.f) atomicMax((int*)addr, __float_as_int(v));
    else          atomicMin((unsigned int*)addr, __float_as_uint(v));
}

__device__ __forceinline__ void atomicAddF4(float* p, float4 v) {
    asm volatile("red.global.add.v4.f32 [%0], {%1, %2, %3, %4};"
                 :: "l"(p), "f"(v.x), "f"(v.y), "f"(v.z), "f"(v.w)
                 : "memory");
}

// ---------------- projection: xs = X@Ws, xd = X@Wd, + attention dots --------
// warp per row; W staged through shared in 64-row chunks (36KB static smem)
__global__ void proj_kernel(const float* __restrict__ X,
                            const float* __restrict__ Ws, const float* __restrict__ Wd,
                            const float* __restrict__ atts, const float* __restrict__ attd,
                            float* __restrict__ xs, float* __restrict__ xd,
                            float* __restrict__ av_s, float* __restrict__ av_d)
{
    __shared__ float Wt[64 * 128];
    __shared__ float sx[8 * 128];
    int w = threadIdx.x >> 5, lane = threadIdx.x & 31;
    int row = blockIdx.x * 8 + w;
    if (row < NN)
        ((float4*)(sx + w * 128))[lane] = ((const float4*)(X + (size_t)row * 128))[lane];

    for (int ph = 0; ph < 2; ph++) {
        const float* W   = ph ? Wd   : Ws;
        const float* att = ph ? attd : atts;
        float acc0 = 0.f, acc1 = 0.f, acc2 = 0.f, acc3 = 0.f;
        for (int kc = 0; kc < 2; kc++) {
            __syncthreads();
            for (int i = threadIdx.x; i < 64 * 128 / 4; i += 256)
                ((float4*)Wt)[i] = ((const float4*)(W + kc * 64 * 128))[i];
            __syncthreads();
            if (row < NN) {
                const float* xr = sx + w * 128 + kc * 64;
                #pragma unroll
                for (int k = 0; k < 64; k++) {
                    float  xv = xr[k];
                    float4 wv = ((const float4*)(Wt + k * 128))[lane];
                    acc0 += xv * wv.x; acc1 += xv * wv.y;
                    acc2 += xv * wv.z; acc3 += xv * wv.w;
                }
            }
        }
        if (row < NN) {
            ((float4*)((ph ? xd : xs) + (size_t)row * 128))[lane] =
                make_float4(acc0, acc1, acc2, acc3);
            // attention dot: flat att index == output column (h*64 + c)
            int col = lane * 4;
            float p = acc0 * att[col] + acc1 * att[col + 1]
                    + acc2 * att[col + 2] + acc3 * att[col + 3];
            #pragma unroll
            for (int off = 8; off; off >>= 1)
                p += __shfl_down_sync(0xffffffffu, p, off, 16);
            float* av = ph ? av_d : av_s;
            if (lane == 0)  av[row * 2 + 0] = p;   // head 0 (cols 0..63)
            if (lane == 16) av[row * 2 + 1] = p;   // head 1 (cols 64..127)
        }
    }
}

// ---------------- per-layer init --------------------------------------------
__global__ void init_layer(float* __restrict__ m, float* __restrict__ den,
                           float* __restrict__ agg)
{
    int i = blockIdx.x * blockDim.x + threadIdx.x;
    if (i < NN * FD) agg[i] = 0.f;
    if (i < NN * HH) { m[i] = __int_as_float(0xff800000); den[i] = 0.f; }
}

// ---------------- edge pass A: logits + segment max -------------------------
__global__ void edgeA(const int* __restrict__ ei,
                      const float* __restrict__ as_, const float* __restrict__ ad_,
                      float* __restrict__ e, float* __restrict__ m)
{
    int t = blockIdx.x * blockDim.x + threadIdx.x;
    if (t >= ET) return;
    int s, d;
    if (t < EE) { s = ei[t]; d = ei[EE + t]; } else { s = d = t - EE; }
    #pragma unroll
    for (int h = 0; h < HH; h++) {
        float v = as_[s * 2 + h] + ad_[d * 2 + h];
        v = v > 0.f ? v : 0.2f * v;                 // leaky_relu
        e[t * 2 + h] = v;
        atomicMaxF(&m[d * 2 + h], v);
    }
}

// ---------------- edge pass B: exp + segment sum -----------------------------
__global__ void edgeB(const int* __restrict__ ei,
                      const float* __restrict__ m,
                      float* __restrict__ e, float* __restrict__ den)
{
    int t = blockIdx.x * blockDim.x + threadIdx.x;
    if (t >= ET) return;
    int d = (t < EE) ? ei[EE + t] : (t - EE);
    #pragma unroll
    for (int h = 0; h < HH; h++) {
        float w = __expf(e[t * 2 + h] - m[d * 2 + h]);
        e[t * 2 + h] = w;
        atomicAdd(&den[d * 2 + h], w);
    }
}

// ---------------- edge pass C: weighted scatter (warp per edge) -------------
__global__ void edgeC(const int* __restrict__ ei,
                      const float* __restrict__ e, const float* __restrict__ den,
                      const float* __restrict__ xs, float* __restrict__ agg)
{
    int gw = (blockIdx.x * blockDim.x + threadIdx.x) >> 5;
    int lane = threadIdx.x & 31;
    if (gw >= ET) return;
    int s, d;
    if (gw < EE) { s = ei[gw]; d = ei[EE + gw]; } else { s = d = gw - EE; }
    float a0 = e[gw * 2 + 0] / den[d * 2 + 0];
    float a1 = e[gw * 2 + 1] / den[d * 2 + 1];
    float alpha = (lane < 16) ? a0 : a1;            // lanes 0..15 = head 0 cols
    float4 v = ((const float4*)(xs + (size_t)s * 128))[lane];
    v.x *= alpha; v.y *= alpha; v.z *= alpha; v.w *= alpha;
    atomicAddF4(agg + (size_t)d * 128 + lane * 4, v);
}

// ---------------- epilogue: + bias, relu -------------------------------------
__global__ void epi(const float* __restrict__ agg, const float* __restrict__ b,
                    float* __restrict__ h)
{
    int i = blockIdx.x * blockDim.x + threadIdx.x;
    if (i < NN * FD) {
        float v = agg[i] + b[i & 127];
        h[i] = v > 0.f ? v : 0.f;
    }
}

// ---------------- pooling -----------------------------------------------------
__global__ void zero_pool(float* __restrict__ pool, float* __restrict__ cnt)
{
    int i = blockIdx.x * blockDim.x + threadIdx.x;
    if (i < GG * FD) pool[i] = 0.f;
    if (i < GG)      cnt[i]  = 0.f;
}

__global__ void pool_kernel(const float* __restrict__ h, const int* __restrict__ batch,
                            float* __restrict__ pool, float* __restrict__ cnt)
{
    int gw = (blockIdx.x * blockDim.x + threadIdx.x) >> 5;
    int lane = threadIdx.x & 31;
    if (gw >= NN) return;
    int g = batch[gw];
    float4 v = ((const float4*)(h + (size_t)gw * 128))[lane];
    atomicAddF4(pool + (size_t)g * 128 + lane * 4, v);
    if (lane == 0) atomicAdd(&cnt[g], 1.f);
}

// ---------------- final linear -------------------------------------------------
__global__ void final_kernel(const float* __restrict__ pool, const float* __restrict__ cnt,
                             const float* __restrict__ Wl, const float* __restrict__ bl,
                             float* __restrict__ out)
{
    __shared__ float row[128];
    int g = blockIdx.x;
    float inv = 1.f / fmaxf(cnt[g], 1.f);
    if (threadIdx.x < 128) row[threadIdx.x] = pool[g * 128 + threadIdx.x] * inv;
    __syncthreads();
    if (threadIdx.x < OUTD) {
        float acc = bl[threadIdx.x];
        #pragma unroll 16
        for (int j = 0; j < 128; j++)
            acc += row[j] * Wl[j * OUTD + threadIdx.x];
        out[g * OUTD + threadIdx.x] = acc;
    }
}

// ---------------- launch ---------------------------------------------------
extern "C" void kernel_launch(void* const* d_in, const int* in_sizes, int n_in,
                              void* d_out, int out_size)
{
    const float* x     = (const float*)d_in[0];
    const int*   ei    = (const int*)  d_in[1];
    const int*   batch = (const int*)  d_in[2];
    const float* Ws1   = (const float*)d_in[3];
    const float* Wd1   = (const float*)d_in[4];
    const float* as1   = (const float*)d_in[5];
    const float* ad1   = (const float*)d_in[6];
    const float* b1    = (const float*)d_in[7];
    const float* Ws2   = (const float*)d_in[8];
    const float* Wd2   = (const float*)d_in[9];
    const float* as2   = (const float*)d_in[10];
    const float* ad2   = (const float*)d_in[11];
    const float* b2    = (const float*)d_in[12];
    const float* Wl    = (const float*)d_in[13];
    const float* bl    = (const float*)d_in[14];
    float* out = (float*)d_out;

    void *p_xs, *p_xd, *p_as, *p_ad, *p_e, *p_m, *p_den, *p_agg, *p_h, *p_pool, *p_cnt;
    cudaGetSymbolAddress(&p_xs,  g_xs);
    cudaGetSymbolAddress(&p_xd,  g_xd);
    cudaGetSymbolAddress(&p_as,  g_as);
    cudaGetSymbolAddress(&p_ad,  g_ad);
    cudaGetSymbolAddress(&p_e,   g_e);
    cudaGetSymbolAddress(&p_m,   g_m);
    cudaGetSymbolAddress(&p_den, g_den);
    cudaGetSymbolAddress(&p_agg, g_agg);
    cudaGetSymbolAddress(&p_h,   g_h);
    cudaGetSymbolAddress(&p_pool,g_pool);
    cudaGetSymbolAddress(&p_cnt, g_cnt);

    float* xs  = (float*)p_xs;  float* xd  = (float*)p_xd;
    float* asv = (float*)p_as;  float* adv = (float*)p_ad;
    float* ev  = (float*)p_e;   float* mv  = (float*)p_m;
    float* den = (float*)p_den; float* agg = (float*)p_agg;
    float* hbuf= (float*)p_h;   float* pool= (float*)p_pool;
    float* cnt = (float*)p_cnt;

    const int PROJ_GRID = (NN + 7) / 8;           // 6250
    const int NODE_GRID = (NN * FD + 255) / 256;  // 25000
    const int EDGE_GRID = (ET + 255) / 256;
    const int EDGEW_GRID = (ET * 32 + 255) / 256;
    const int POOLW_GRID = (NN * 32 + 255) / 256;

    // ---- layer 1 ----
    proj_kernel<<<PROJ_GRID, 256>>>(x, Ws1, Wd1, as1, ad1, xs, xd, asv, adv);
    init_layer<<<NODE_GRID, 256>>>(mv, den, agg);
    edgeA<<<EDGE_GRID, 256>>>(ei, asv, adv, ev, mv);
    edgeB<<<EDGE_GRID, 256>>>(ei, mv, ev, den);
    edgeC<<<EDGEW_GRID, 256>>>(ei, ev, den, xs, agg);
    epi<<<NODE_GRID, 256>>>(agg, b1, hbuf);

    // ---- layer 2 ----
    proj_kernel<<<PROJ_GRID, 256>>>(hbuf, Ws2, Wd2, as2, ad2, xs, xd, asv, adv);
    init_layer<<<NODE_GRID, 256>>>(mv, den, agg);
    edgeA<<<EDGE_GRID, 256>>>(ei, asv, adv, ev, mv);
    edgeB<<<EDGE_GRID, 256>>>(ei, mv, ev, den);
    edgeC<<<EDGEW_GRID, 256>>>(ei, ev, den, xs, agg);
    epi<<<NODE_GRID, 256>>>(agg, b2, hbuf);

    // ---- pooling + final linear ----
    zero_pool<<<(GG * FD + 255) / 256, 256>>>(pool, cnt);
    pool_kernel<<<POOLW_GRID, 256>>>(hbuf, batch, pool, cnt);
    final_kernel<<<GG, 128>>>(pool, cnt, Wl, bl, out);
}

// round 2
// speedup vs baseline: 2.4207x; 2.4207x over previous
#include <cuda_runtime.h>
#include <cuda_bf16.h>

#define NN   50000
#define EE   800000
#define ET   (EE + NN)        // edges incl. self loops = 850000
#define FD   128
#define HH   2
#define GG   64
#define OUTD 10
#define SBLK ((NN + 1023) / 1024)   // 49 scan blocks

// ---------------- scratch (device globals; no allocation allowed) ----------
__device__ float g_xs [NN * FD];     // source projection
__device__ float g_xd [NN * FD];     // dest projection
__device__ float g_as [NN * HH];     // per-node source attention logit
__device__ float g_ad [NN * HH];     // per-node dest attention logit
__device__ float g_h  [NN * FD];     // layer output
__device__ float g_pool[GG * FD];
__device__ float g_cnt [GG];
// CSR
__device__ int g_deg   [NN];
__device__ int g_rowptr[NN + 1];
__device__ int g_cursor[NN];
__device__ int g_col   [ET];
__device__ int g_bsum  [SBLK];

__device__ __forceinline__ void atomicAddF4(float* p, float4 v) {
    asm volatile("red.global.add.v4.f32 [%0], {%1, %2, %3, %4};"
                 :: "l"(p), "f"(v.x), "f"(v.y), "f"(v.z), "f"(v.w)
                 : "memory");
}

// ================= CSR build (edge index is launch-invariant) ===============
__global__ void csr_zero(int* __restrict__ deg) {
    int i = blockIdx.x * blockDim.x + threadIdx.x;
    if (i < NN) deg[i] = 0;
}

__global__ void csr_hist(const int* __restrict__ ei, int* __restrict__ deg) {
    int t = blockIdx.x * blockDim.x + threadIdx.x;
    if (t >= ET) return;
    int d = (t < EE) ? ei[EE + t] : (t - EE);
    atomicAdd(&deg[d], 1);
}

__global__ void scan_block(const int* __restrict__ deg, int* __restrict__ rowptr,
                           int* __restrict__ bsum) {
    __shared__ int sh[1024];
    int i = blockIdx.x * 1024 + threadIdx.x;
    int v = (i < NN) ? deg[i] : 0;
    sh[threadIdx.x] = v;
    __syncthreads();
    #pragma unroll
    for (int s = 1; s < 1024; s <<= 1) {
        int t = (threadIdx.x >= s) ? sh[threadIdx.x - s] : 0;
        __syncthreads();
        sh[threadIdx.x] += t;
        __syncthreads();
    }
    if (i < NN) rowptr[i] = sh[threadIdx.x] - v;     // exclusive within block
    if (threadIdx.x == 1023) bsum[blockIdx.x] = sh[1023];
}

__global__ void scan_sums(int* __restrict__ bsum) {
    __shared__ int sh[64];
    int tid = threadIdx.x;
    int v = (tid < SBLK) ? bsum[tid] : 0;
    sh[tid] = v;
    __syncthreads();
    #pragma unroll
    for (int s = 1; s < 64; s <<= 1) {
        int t = (tid >= s) ? sh[tid - s] : 0;
        __syncthreads();
        sh[tid] += t;
        __syncthreads();
    }
    if (tid < SBLK) bsum[tid] = sh[tid] - v;          // exclusive
}

__global__ void csr_finalize(const int* __restrict__ bsum, int* __restrict__ rowptr,
                             int* __restrict__ cursor) {
    int i = blockIdx.x * blockDim.x + threadIdx.x;
    if (i < NN) {
        int v = rowptr[i] + bsum[i >> 10];
        rowptr[i] = v;
        cursor[i] = v;
    }
    if (i == 0) rowptr[NN] = ET;
}

__global__ void csr_fill(const int* __restrict__ ei, int* __restrict__ cursor,
                         int* __restrict__ col) {
    int t = blockIdx.x * blockDim.x + threadIdx.x;
    if (t >= ET) return;
    int s, d;
    if (t < EE) { s = ei[t]; d = ei[EE + t]; } else { s = d = t - EE; }
    int pos = atomicAdd(&cursor[d], 1);
    col[pos] = s;
}

// ================= projection: xs=X@Ws, xd=X@Wd, + attention dots ============
// 8 warps/block, 8 rows/warp -> 64 rows/block. 32 FMAs per 512B W read.
__global__ void __launch_bounds__(256) proj_kernel(
        const float* __restrict__ X,
        const float* __restrict__ Ws, const float* __restrict__ Wd,
        const float* __restrict__ atts, const float* __restrict__ attd,
        float* __restrict__ xs, float* __restrict__ xd,
        float* __restrict__ av_s, float* __restrict__ av_d)
{
    __shared__ float Wt[32 * 128];   // 16KB chunk of W
    __shared__ float sx[64 * 128];   // 32KB of X rows
    int w = threadIdx.x >> 5, lane = threadIdx.x & 31;
    int rowBase = blockIdx.x * 64;

    for (int i = threadIdx.x; i < 64 * 32; i += 256) {      // float4 granularity
        int r = i >> 5, c = i & 31;
        if (rowBase + r < NN)
            ((float4*)sx)[i] = ((const float4*)(X + (size_t)(rowBase + r) * 128))[c];
    }

    #pragma unroll 1
    for (int ph = 0; ph < 2; ph++) {
        const float* W   = ph ? Wd   : Ws;
        const float* att = ph ? attd : atts;
        float4 acc[8];
        #pragma unroll
        for (int r = 0; r < 8; r++) acc[r] = make_float4(0.f, 0.f, 0.f, 0.f);

        #pragma unroll 1
        for (int kc = 0; kc < 4; kc++) {
            __syncthreads();
            for (int i = threadIdx.x; i < 32 * 32; i += 256)
                ((float4*)Wt)[i] = ((const float4*)(W + kc * 32 * 128))[i];
            __syncthreads();
            const float* xr = sx + (w * 8) * 128 + kc * 32;
            #pragma unroll
            for (int k = 0; k < 32; k++) {
                float4 wv = ((const float4*)(Wt + k * 128))[lane];
                #pragma unroll
                for (int r = 0; r < 8; r++) {
                    float xv = xr[r * 128 + k];
                    acc[r].x += xv * wv.x; acc[r].y += xv * wv.y;
                    acc[r].z += xv * wv.z; acc[r].w += xv * wv.w;
                }
            }
        }

        #pragma unroll
        for (int r = 0; r < 8; r++) {
            int row = rowBase + w * 8 + r;
            if (row >= NN) continue;
            ((float4*)((ph ? xd : xs) + (size_t)row * 128))[lane] = acc[r];
            int colb = lane * 4;
            float p = acc[r].x * att[colb]     + acc[r].y * att[colb + 1]
                    + acc[r].z * att[colb + 2] + acc[r].w * att[colb + 3];
            #pragma unroll
            for (int off = 8; off; off >>= 1)
                p += __shfl_down_sync(0xffffffffu, p, off, 16);
            float* av = ph ? av_d : av_s;
            if (lane == 0)  av[row * 2 + 0] = p;   // head 0 (cols 0..63)
            if (lane == 16) av[row * 2 + 1] = p;   // head 1 (cols 64..127)
        }
    }
}

// ================= fused GAT aggregation: warp per destination node ==========
// softmax (max+sum) in registers, gather xs[src], bias+ReLU epilogue fused.
__device__ __forceinline__ float lrelu(float v) { return v > 0.f ? v : 0.2f * v; }

__global__ void __launch_bounds__(256) gat_agg(
        const int* __restrict__ rowptr, const int* __restrict__ col,
        const float* __restrict__ a_s, const float* __restrict__ a_d,
        const float* __restrict__ xs,  const float* __restrict__ b,
        float* __restrict__ out)
{
    int n = blockIdx.x * 8 + (threadIdx.x >> 5);
    int lane = threadIdx.x & 31;
    if (n >= NN) return;
    int r0 = rowptr[n], r1 = rowptr[n + 1];
    float ad0 = a_d[n * 2], ad1 = a_d[n * 2 + 1];

    // phase 1: max over incoming edges (both heads)
    float m0 = -1e30f, m1 = -1e30f;
    for (int j = r0 + lane; j < r1; j += 32) {
        int s = col[j];
        m0 = fmaxf(m0, lrelu(a_s[s * 2]     + ad0));
        m1 = fmaxf(m1, lrelu(a_s[s * 2 + 1] + ad1));
    }
    #pragma unroll
    for (int off = 16; off; off >>= 1) {
        m0 = fmaxf(m0, __shfl_xor_sync(0xffffffffu, m0, off));
        m1 = fmaxf(m1, __shfl_xor_sync(0xffffffffu, m1, off));
    }
    // phase 2: denom
    float d0 = 0.f, d1 = 0.f;
    for (int j = r0 + lane; j < r1; j += 32) {
        int s = col[j];
        d0 += __expf(lrelu(a_s[s * 2]     + ad0) - m0);
        d1 += __expf(lrelu(a_s[s * 2 + 1] + ad1) - m1);
    }
    #pragma unroll
    for (int off = 16; off; off >>= 1) {
        d0 += __shfl_xor_sync(0xffffffffu, d0, off);
        d1 += __shfl_xor_sync(0xffffffffu, d1, off);
    }
    int h = lane >> 4;                       // lanes 0..15 head0, 16..31 head1
    float adh  = h ? ad1 : ad0;
    float mh   = h ? m1  : m0;
    float invh = 1.f / (h ? d1 : d0);

    // phase 3: weighted gather, full warp per edge
    float4 acc = make_float4(0.f, 0.f, 0.f, 0.f);
    for (int j = r0; j < r1; j++) {
        int s = col[j];                      // broadcast load
        float w = __expf(lrelu(a_s[s * 2 + h] + adh) - mh) * invh;
        float4 v = ((const float4*)(xs + (size_t)s * 128))[lane];
        acc.x += w * v.x; acc.y += w * v.y; acc.z += w * v.z; acc.w += w * v.w;
    }
    float4 bb = ((const float4*)b)[lane];
    acc.x = fmaxf(acc.x + bb.x, 0.f);
    acc.y = fmaxf(acc.y + bb.y, 0.f);
    acc.z = fmaxf(acc.z + bb.z, 0.f);
    acc.w = fmaxf(acc.w + bb.w, 0.f);
    ((float4*)(out + (size_t)n * 128))[lane] = acc;
}

// ================= pooling + final linear =====================================
__global__ void zero_pool(float* __restrict__ pool, float* __restrict__ cnt) {
    int i = blockIdx.x * blockDim.x + threadIdx.x;
    if (i < GG * FD) pool[i] = 0.f;
    if (i < GG)      cnt[i]  = 0.f;
}

__global__ void pool_kernel(const float* __restrict__ h, const int* __restrict__ batch,
                            float* __restrict__ pool, float* __restrict__ cnt) {
    int gw = (blockIdx.x * blockDim.x + threadIdx.x) >> 5;
    int lane = threadIdx.x & 31;
    if (gw >= NN) return;
    int g = batch[gw];
    float4 v = ((const float4*)(h + (size_t)gw * 128))[lane];
    atomicAddF4(pool + (size_t)g * 128 + lane * 4, v);
    if (lane == 0) atomicAdd(&cnt[g], 1.f);
}

__global__ void final_kernel(const float* __restrict__ pool, const float* __restrict__ cnt,
                             const float* __restrict__ Wl, const float* __restrict__ bl,
                             float* __restrict__ out) {
    __shared__ float row[128];
    int g = blockIdx.x;
    float inv = 1.f / fmaxf(cnt[g], 1.f);
    if (threadIdx.x < 128) row[threadIdx.x] = pool[g * 128 + threadIdx.x] * inv;
    __syncthreads();
    if (threadIdx.x < OUTD) {
        float acc = bl[threadIdx.x];
        #pragma unroll 16
        for (int j = 0; j < 128; j++)
            acc += row[j] * Wl[j * OUTD + threadIdx.x];
        out[g * OUTD + threadIdx.x] = acc;
    }
}

// ================= launch =====================================================
extern "C" void kernel_launch(void* const* d_in, const int* in_sizes, int n_in,
                              void* d_out, int out_size)
{
    const float* x     = (const float*)d_in[0];
    const int*   ei    = (const int*)  d_in[1];
    const int*   batch = (const int*)  d_in[2];
    const float* Ws1   = (const float*)d_in[3];
    const float* Wd1   = (const float*)d_in[4];
    const float* as1   = (const float*)d_in[5];
    const float* ad1   = (const float*)d_in[6];
    const float* b1    = (const float*)d_in[7];
    const float* Ws2   = (const float*)d_in[8];
    const float* Wd2   = (const float*)d_in[9];
    const float* as2   = (const float*)d_in[10];
    const float* ad2   = (const float*)d_in[11];
    const float* b2    = (const float*)d_in[12];
    const float* Wl    = (const float*)d_in[13];
    const float* bl    = (const float*)d_in[14];
    float* out = (float*)d_out;

    void *p_xs, *p_xd, *p_as, *p_ad, *p_h, *p_pool, *p_cnt;
    void *p_deg, *p_rowptr, *p_cursor, *p_col, *p_bsum;
    cudaGetSymbolAddress(&p_xs,  g_xs);
    cudaGetSymbolAddress(&p_xd,  g_xd);
    cudaGetSymbolAddress(&p_as,  g_as);
    cudaGetSymbolAddress(&p_ad,  g_ad);
    cudaGetSymbolAddress(&p_h,   g_h);
    cudaGetSymbolAddress(&p_pool,g_pool);
    cudaGetSymbolAddress(&p_cnt, g_cnt);
    cudaGetSymbolAddress(&p_deg,    g_deg);
    cudaGetSymbolAddress(&p_rowptr, g_rowptr);
    cudaGetSymbolAddress(&p_cursor, g_cursor);
    cudaGetSymbolAddress(&p_col,    g_col);
    cudaGetSymbolAddress(&p_bsum,   g_bsum);

    float* xs  = (float*)p_xs;  float* xd  = (float*)p_xd;
    float* asv = (float*)p_as;  float* adv = (float*)p_ad;
    float* hbuf= (float*)p_h;   float* pool= (float*)p_pool;
    float* cnt = (float*)p_cnt;
    int* deg    = (int*)p_deg;    int* rowptr = (int*)p_rowptr;
    int* cursor = (int*)p_cursor; int* col    = (int*)p_col;
    int* bsum   = (int*)p_bsum;

    const int PROJ_GRID = (NN + 63) / 64;         // 782
    const int AGG_GRID  = (NN + 7) / 8;           // 6250
    const int EDGE_GRID = (ET + 255) / 256;
    const int NODE_GRID = (NN + 255) / 256;
    const int POOLW_GRID = (NN * 32 + 255) / 256;

    // ---- CSR build (once; edge index identical for both layers) ----
    csr_zero<<<NODE_GRID, 256>>>(deg);
    csr_hist<<<EDGE_GRID, 256>>>(ei, deg);
    scan_block<<<SBLK, 1024>>>(deg, rowptr, bsum);
    scan_sums<<<1, 64>>>(bsum);
    csr_finalize<<<NODE_GRID, 256>>>(bsum, rowptr, cursor);
    csr_fill<<<EDGE_GRID, 256>>>(ei, cursor, col);

    // ---- layer 1 ----
    proj_kernel<<<PROJ_GRID, 256>>>(x, Ws1, Wd1, as1, ad1, xs, xd, asv, adv);
    gat_agg<<<AGG_GRID, 256>>>(rowptr, col, asv, adv, xs, b1, hbuf);

    // ---- layer 2 ----
    proj_kernel<<<PROJ_GRID, 256>>>(hbuf, Ws2, Wd2, as2, ad2, xs, xd, asv, adv);
    gat_agg<<<AGG_GRID, 256>>>(rowptr, col, asv, adv, xs, b2, hbuf);

    // ---- pooling + final linear ----
    zero_pool<<<(GG * FD + 255) / 256, 256>>>(pool, cnt);
    pool_kernel<<<POOLW_GRID, 256>>>(hbuf, batch, pool, cnt);
    final_kernel<<<GG, 128>>>(pool, cnt, Wl, bl, out);
}

// round 3
// speedup vs baseline: 2.8592x; 1.1811x over previous
#include <cuda_runtime.h>
#include <cuda_bf16.h>

#define NN   50000
#define EE   800000
#define ET   (EE + NN)        // edges incl. self loops = 850000
#define FD   128
#define HH   2
#define GG   64
#define OUTD 10
#define SBLK ((NN + 1023) / 1024)   // 49 scan blocks

// ---------------- scratch (device globals; no allocation allowed) ----------
__device__ float g_xs [NN * FD];     // source projection
__device__ float g_as [NN * HH];     // per-node source attention logit
__device__ float g_ad [NN * HH];     // per-node dest attention logit
__device__ float g_h  [NN * FD];     // layer output
__device__ float g_pool[GG * FD];
__device__ float g_cnt [GG];
__device__ float g_vd1 [FD * HH];    // Wd1 @ ad1 (folded dest attention)
__device__ float g_vd2 [FD * HH];    // Wd2 @ ad2
// CSR
__device__ int g_deg   [NN];
__device__ int g_rowptr[NN + 1];
__device__ int g_cursor[NN];
__device__ int g_col   [ET];
__device__ int g_bsum  [SBLK];

__device__ __forceinline__ void atomicAddF4(float* p, float4 v) {
    asm volatile("red.global.add.v4.f32 [%0], {%1, %2, %3, %4};"
                 :: "l"(p), "f"(v.x), "f"(v.y), "f"(v.z), "f"(v.w)
                 : "memory");
}

// ================= CSR build (edge index is launch-invariant) ===============
__global__ void csr_hist(const int* __restrict__ ei, int* __restrict__ deg) {
    int t = blockIdx.x * blockDim.x + threadIdx.x;
    if (t >= ET) return;
    int d = (t < EE) ? ei[EE + t] : (t - EE);
    atomicAdd(&deg[d], 1);
}

__global__ void scan_block(const int* __restrict__ deg, int* __restrict__ rowptr,
                           int* __restrict__ bsum) {
    __shared__ int sh[1024];
    int i = blockIdx.x * 1024 + threadIdx.x;
    int v = (i < NN) ? deg[i] : 0;
    sh[threadIdx.x] = v;
    __syncthreads();
    #pragma unroll
    for (int s = 1; s < 1024; s <<= 1) {
        int t = (threadIdx.x >= s) ? sh[threadIdx.x - s] : 0;
        __syncthreads();
        sh[threadIdx.x] += t;
        __syncthreads();
    }
    if (i < NN) rowptr[i] = sh[threadIdx.x] - v;     // exclusive within block
    if (threadIdx.x == 1023) bsum[blockIdx.x] = sh[1023];
}

__global__ void scan_sums(int* __restrict__ bsum) {
    __shared__ int sh[64];
    int tid = threadIdx.x;
    int v = (tid < SBLK) ? bsum[tid] : 0;
    sh[tid] = v;
    __syncthreads();
    #pragma unroll
    for (int s = 1; s < 64; s <<= 1) {
        int t = (tid >= s) ? sh[tid - s] : 0;
        __syncthreads();
        sh[tid] += t;
        __syncthreads();
    }
    if (tid < SBLK) bsum[tid] = sh[tid] - v;          // exclusive
}

__global__ void csr_finalize(const int* __restrict__ bsum, int* __restrict__ rowptr,
                             int* __restrict__ cursor) {
    int i = blockIdx.x * blockDim.x + threadIdx.x;
    if (i < NN) {
        int v = rowptr[i] + bsum[i >> 10];
        rowptr[i] = v;
        cursor[i] = v;
    }
    if (i == 0) rowptr[NN] = ET;
}

__global__ void csr_fill(const int* __restrict__ ei, int* __restrict__ cursor,
                         int* __restrict__ col) {
    int t = blockIdx.x * blockDim.x + threadIdx.x;
    if (t >= ET) return;
    int s, d;
    if (t < EE) { s = ei[t]; d = ei[EE + t]; } else { s = d = t - EE; }
    int pos = atomicAdd(&cursor[d], 1);
    col[pos] = s;
}

// ================= attention folding: vd = Wd @ ad (per head) ================
__global__ void make_vd(const float* __restrict__ Wd, const float* __restrict__ ad,
                        float* __restrict__ vd) {
    int k = threadIdx.x;                 // 128 threads, one per input dim
    #pragma unroll
    for (int h = 0; h < HH; h++) {
        float s = 0.f;
        #pragma unroll 16
        for (int c = 0; c < 64; c++)
            s += Wd[k * 128 + h * 64 + c] * ad[h * 64 + c];
        vd[k * 2 + h] = s;
    }
}

// ================= projection: xs=X@Ws, a_s = xs·atts, a_d = X·vd ============
// 8 warps/block, 8 rows/warp -> 64 rows/block. 32 FMAs per 512B W read.
__global__ void __launch_bounds__(256) proj_kernel(
        const float* __restrict__ X,
        const float* __restrict__ Ws,
        const float* __restrict__ atts, const float* __restrict__ vd,
        float* __restrict__ xs,
        float* __restrict__ av_s, float* __restrict__ av_d)
{
    __shared__ float Wt[32 * 128];   // 16KB chunk of Ws
    __shared__ float sx[64 * 128];   // 32KB of X rows
    __shared__ float svd[256];
    int w = threadIdx.x >> 5, lane = threadIdx.x & 31;
    int rowBase = blockIdx.x * 64;

    if (threadIdx.x < 256) svd[threadIdx.x] = vd[threadIdx.x];
    for (int i = threadIdx.x; i < 64 * 32; i += 256) {      // float4 granularity
        int r = i >> 5, c = i & 31;
        if (rowBase + r < NN)
            ((float4*)sx)[i] = ((const float4*)(X + (size_t)(rowBase + r) * 128))[c];
    }

    float4 acc[8];
    #pragma unroll
    for (int r = 0; r < 8; r++) acc[r] = make_float4(0.f, 0.f, 0.f, 0.f);

    #pragma unroll 1
    for (int kc = 0; kc < 4; kc++) {
        __syncthreads();
        for (int i = threadIdx.x; i < 32 * 32; i += 256)
            ((float4*)Wt)[i] = ((const float4*)(Ws + kc * 32 * 128))[i];
        __syncthreads();
        const float* xr = sx + (w * 8) * 128 + kc * 32;
        #pragma unroll
        for (int k = 0; k < 32; k++) {
            float4 wv = ((const float4*)(Wt + k * 128))[lane];
            #pragma unroll
            for (int r = 0; r < 8; r++) {
                float xv = xr[r * 128 + k];
                acc[r].x += xv * wv.x; acc[r].y += xv * wv.y;
                acc[r].z += xv * wv.z; acc[r].w += xv * wv.w;
            }
        }
    }

    #pragma unroll
    for (int r = 0; r < 8; r++) {
        int row = rowBase + w * 8 + r;
        if (row >= NN) continue;
        ((float4*)(xs + (size_t)row * 128))[lane] = acc[r];

        // a_s = xs_row · atts (per head; lanes 0..15 = head0 cols, 16..31 = head1)
        int colb = lane * 4;
        float p = acc[r].x * atts[colb]     + acc[r].y * atts[colb + 1]
                + acc[r].z * atts[colb + 2] + acc[r].w * atts[colb + 3];
        #pragma unroll
        for (int off = 8; off; off >>= 1)
            p += __shfl_down_sync(0xffffffffu, p, off, 16);
        if (lane == 0)  av_s[row * 2 + 0] = p;
        if (lane == 16) av_s[row * 2 + 1] = p;

        // a_d = X_row · vd (both heads, full-warp reduction)
        float4 xv = ((const float4*)(sx + (w * 8 + r) * 128))[lane];
        int kb = lane * 4;
        float pd0 = xv.x * svd[2 * kb + 0] + xv.y * svd[2 * (kb + 1) + 0]
                  + xv.z * svd[2 * (kb + 2) + 0] + xv.w * svd[2 * (kb + 3) + 0];
        float pd1 = xv.x * svd[2 * kb + 1] + xv.y * svd[2 * (kb + 1) + 1]
                  + xv.z * svd[2 * (kb + 2) + 1] + xv.w * svd[2 * (kb + 3) + 1];
        #pragma unroll
        for (int off = 16; off; off >>= 1) {
            pd0 += __shfl_xor_sync(0xffffffffu, pd0, off);
            pd1 += __shfl_xor_sync(0xffffffffu, pd1, off);
        }
        if (lane == 0) {
            av_d[row * 2 + 0] = pd0;
            av_d[row * 2 + 1] = pd1;
        }
    }
}

// ================= fused GAT aggregation: warp per destination node ==========
__device__ __forceinline__ float lrelu(float v) { return v > 0.f ? v : 0.2f * v; }

__global__ void __launch_bounds__(256) gat_agg(
        const int* __restrict__ rowptr, const int* __restrict__ col,
        const float* __restrict__ a_s, const float* __restrict__ a_d,
        const float* __restrict__ xs,  const float* __restrict__ b,
        float* __restrict__ out)
{
    int n = blockIdx.x * 8 + (threadIdx.x >> 5);
    int lane = threadIdx.x & 31;
    if (n >= NN) return;
    int r0 = rowptr[n], r1 = rowptr[n + 1];
    float ad0 = a_d[n * 2], ad1 = a_d[n * 2 + 1];

    // phase 1: max over incoming edges (both heads)
    float m0 = -1e30f, m1 = -1e30f;
    for (int j = r0 + lane; j < r1; j += 32) {
        int s = col[j];
        m0 = fmaxf(m0, lrelu(a_s[s * 2]     + ad0));
        m1 = fmaxf(m1, lrelu(a_s[s * 2 + 1] + ad1));
    }
    #pragma unroll
    for (int off = 16; off; off >>= 1) {
        m0 = fmaxf(m0, __shfl_xor_sync(0xffffffffu, m0, off));
        m1 = fmaxf(m1, __shfl_xor_sync(0xffffffffu, m1, off));
    }
    // phase 2: denom
    float d0 = 0.f, d1 = 0.f;
    for (int j = r0 + lane; j < r1; j += 32) {
        int s = col[j];
        d0 += __expf(lrelu(a_s[s * 2]     + ad0) - m0);
        d1 += __expf(lrelu(a_s[s * 2 + 1] + ad1) - m1);
    }
    #pragma unroll
    for (int off = 16; off; off >>= 1) {
        d0 += __shfl_xor_sync(0xffffffffu, d0, off);
        d1 += __shfl_xor_sync(0xffffffffu, d1, off);
    }
    int h = lane >> 4;                       // lanes 0..15 head0, 16..31 head1
    float adh  = h ? ad1 : ad0;
    float mh   = h ? m1  : m0;
    float invh = 1.f / (h ? d1 : d0);

    // phase 3: weighted gather, full warp per edge
    float4 acc = make_float4(0.f, 0.f, 0.f, 0.f);
    for (int j = r0; j < r1; j++) {
        int s = col[j];                      // broadcast load
        float w = __expf(lrelu(a_s[s * 2 + h] + adh) - mh) * invh;
        float4 v = ((const float4*)(xs + (size_t)s * 128))[lane];
        acc.x += w * v.x; acc.y += w * v.y; acc.z += w * v.z; acc.w += w * v.w;
    }
    float4 bb = ((const float4*)b)[lane];
    acc.x = fmaxf(acc.x + bb.x, 0.f);
    acc.y = fmaxf(acc.y + bb.y, 0.f);
    acc.z = fmaxf(acc.z + bb.z, 0.f);
    acc.w = fmaxf(acc.w + bb.w, 0.f);
    ((float4*)(out + (size_t)n * 128))[lane] = acc;
}

// ================= pooling + final linear =====================================
__global__ void pool_kernel(const float* __restrict__ h, const int* __restrict__ batch,
                            float* __restrict__ pool, float* __restrict__ cnt) {
    int gw = (blockIdx.x * blockDim.x + threadIdx.x) >> 5;
    int lane = threadIdx.x & 31;
    if (gw >= NN) return;
    int g = batch[gw];
    float4 v = ((const float4*)(h + (size_t)gw * 128))[lane];
    atomicAddF4(pool + (size_t)g * 128 + lane * 4, v);
    if (lane == 0) atomicAdd(&cnt[g], 1.f);
}

__global__ void final_kernel(const float* __restrict__ pool, const float* __restrict__ cnt,
                             const float* __restrict__ Wl, const float* __restrict__ bl,
                             float* __restrict__ out) {
    __shared__ float row[128];
    int g = blockIdx.x;
    float inv = 1.f / fmaxf(cnt[g], 1.f);
    if (threadIdx.x < 128) row[threadIdx.x] = pool[g * 128 + threadIdx.x] * inv;
    __syncthreads();
    if (threadIdx.x < OUTD) {
        float acc = bl[threadIdx.x];
        #pragma unroll 16
        for (int j = 0; j < 128; j++)
            acc += row[j] * Wl[j * OUTD + threadIdx.x];
        out[g * OUTD + threadIdx.x] = acc;
    }
}

// ================= launch =====================================================
extern "C" void kernel_launch(void* const* d_in, const int* in_sizes, int n_in,
                              void* d_out, int out_size)
{
    const float* x     = (const float*)d_in[0];
    const int*   ei    = (const int*)  d_in[1];
    const int*   batch = (const int*)  d_in[2];
    const float* Ws1   = (const float*)d_in[3];
    const float* Wd1   = (const float*)d_in[4];
    const float* as1   = (const float*)d_in[5];
    const float* ad1   = (const float*)d_in[6];
    const float* b1    = (const float*)d_in[7];
    const float* Ws2   = (const float*)d_in[8];
    const float* Wd2   = (const float*)d_in[9];
    const float* as2   = (const float*)d_in[10];
    const float* ad2   = (const float*)d_in[11];
    const float* b2    = (const float*)d_in[12];
    const float* Wl    = (const float*)d_in[13];
    const float* bl    = (const float*)d_in[14];
    float* out = (float*)d_out;

    void *p_xs, *p_as, *p_ad, *p_h, *p_pool, *p_cnt, *p_vd1, *p_vd2;
    void *p_deg, *p_rowptr, *p_cursor, *p_col, *p_bsum;
    cudaGetSymbolAddress(&p_xs,  g_xs);
    cudaGetSymbolAddress(&p_as,  g_as);
    cudaGetSymbolAddress(&p_ad,  g_ad);
    cudaGetSymbolAddress(&p_h,   g_h);
    cudaGetSymbolAddress(&p_pool,g_pool);
    cudaGetSymbolAddress(&p_cnt, g_cnt);
    cudaGetSymbolAddress(&p_vd1, g_vd1);
    cudaGetSymbolAddress(&p_vd2, g_vd2);
    cudaGetSymbolAddress(&p_deg,    g_deg);
    cudaGetSymbolAddress(&p_rowptr, g_rowptr);
    cudaGetSymbolAddress(&p_cursor, g_cursor);
    cudaGetSymbolAddress(&p_col,    g_col);
    cudaGetSymbolAddress(&p_bsum,   g_bsum);

    float* xs  = (float*)p_xs;
    float* asv = (float*)p_as;  float* adv = (float*)p_ad;
    float* hbuf= (float*)p_h;   float* pool= (float*)p_pool;
    float* cnt = (float*)p_cnt;
    float* vd1 = (float*)p_vd1; float* vd2 = (float*)p_vd2;
    int* deg    = (int*)p_deg;    int* rowptr = (int*)p_rowptr;
    int* cursor = (int*)p_cursor; int* col    = (int*)p_col;
    int* bsum   = (int*)p_bsum;

    const int PROJ_GRID = (NN + 63) / 64;         // 782
    const int AGG_GRID  = (NN + 7) / 8;           // 6250
    const int EDGE_GRID = (ET + 255) / 256;
    const int NODE_GRID = (NN + 255) / 256;
    const int POOLW_GRID = (NN * 32 + 255) / 256;

    // ---- CSR build (once; edge index identical for both layers) ----
    cudaMemsetAsync(deg, 0, NN * sizeof(int));
    csr_hist<<<EDGE_GRID, 256>>>(ei, deg);
    scan_block<<<SBLK, 1024>>>(deg, rowptr, bsum);
    scan_sums<<<1, 64>>>(bsum);
    csr_finalize<<<NODE_GRID, 256>>>(bsum, rowptr, cursor);
    csr_fill<<<EDGE_GRID, 256>>>(ei, cursor, col);

    // ---- folded dest-attention vectors ----
    make_vd<<<1, 128>>>(Wd1, ad1, vd1);
    make_vd<<<1, 128>>>(Wd2, ad2, vd2);

    // ---- layer 1 ----
    proj_kernel<<<PROJ_GRID, 256>>>(x, Ws1, as1, vd1, xs, asv, adv);
    gat_agg<<<AGG_GRID, 256>>>(rowptr, col, asv, adv, xs, b1, hbuf);

    // ---- layer 2 ----
    proj_kernel<<<PROJ_GRID, 256>>>(hbuf, Ws2, as2, vd2, xs, asv, adv);
    gat_agg<<<AGG_GRID, 256>>>(rowptr, col, asv, adv, xs, b2, hbuf);

    // ---- pooling + final linear ----
    cudaMemsetAsync(pool, 0, (GG * FD + GG) * 0);  // no-op guard (sizes differ)
    cudaMemsetAsync(pool, 0, GG * FD * sizeof(float));
    cudaMemsetAsync(cnt,  0, GG * sizeof(float));
    pool_kernel<<<POOLW_GRID, 256>>>(hbuf, batch, pool, cnt);
    final_kernel<<<GG, 128>>>(pool, cnt, Wl, bl, out);
}

// round 4
// speedup vs baseline: 2.8892x; 1.0105x over previous
#include <cuda_runtime.h>
#include <cuda_bf16.h>

#define NN   50000
#define EE   800000
#define ET   (EE + NN)        // edges incl. self loops = 850000
#define FD   128
#define HH   2
#define GG   64
#define OUTD 10

typedef unsigned long long u64;

// ---------------- scratch (device globals; no allocation allowed) ----------
__device__ float g_xs [NN * FD];     // source projection
__device__ float g_as [NN * HH];     // per-node source attention logit
__device__ float g_ad [NN * HH];     // per-node dest attention logit
__device__ float g_h  [NN * FD];     // layer output
__device__ float g_vd1 [FD * HH];    // Wd1 @ ad1 (folded dest attention)
__device__ float g_vd2 [FD * HH];    // Wd2 @ ad2
// CSR
__device__ int g_deg   [NN];
__device__ int g_rowptr[NN + 1];
__device__ int g_cursor[NN];
__device__ int g_col   [ET];

// ---------------- f32x2 helpers ---------------------------------------------
__device__ __forceinline__ u64 pk2(float lo, float hi) {
    u64 r; asm("mov.b64 %0, {%1, %2};" : "=l"(r) : "f"(lo), "f"(hi)); return r;
}
__device__ __forceinline__ void unpk2(float& lo, float& hi, u64 v) {
    asm("mov.b64 {%0, %1}, %2;" : "=f"(lo), "=f"(hi) : "l"(v));
}
__device__ __forceinline__ u64 fma2(u64 a, u64 b, u64 c) {
    u64 d; asm("fma.rn.f32x2 %0, %1, %2, %3;" : "=l"(d) : "l"(a), "l"(b), "l"(c));
    return d;
}

// ================= prelude: zero deg + folded dest-attention vectors =========
__global__ void prelude(const float* __restrict__ Wd1, const float* __restrict__ ad1,
                        float* __restrict__ vd1,
                        const float* __restrict__ Wd2, const float* __restrict__ ad2,
                        float* __restrict__ vd2,
                        int* __restrict__ deg)
{
    int i = blockIdx.x * blockDim.x + threadIdx.x;
    for (int j = i; j < NN; j += gridDim.x * blockDim.x) deg[j] = 0;
    if (blockIdx.x < 2 && threadIdx.x < 128) {
        const float* Wd = blockIdx.x ? Wd2 : Wd1;
        const float* ad = blockIdx.x ? ad2 : ad1;
        float*       vd = blockIdx.x ? vd2 : vd1;
        int k = threadIdx.x;
        #pragma unroll
        for (int h = 0; h < HH; h++) {
            float s = 0.f;
            #pragma unroll 16
            for (int c = 0; c < 64; c++)
                s += Wd[k * 128 + h * 64 + c] * ad[h * 64 + c];
            vd[k * 2 + h] = s;
        }
    }
}

// ================= CSR build ==================================================
__global__ void csr_hist(const int* __restrict__ ei, int* __restrict__ deg) {
    int t = blockIdx.x * blockDim.x + threadIdx.x;
    if (t >= ET) return;
    int d = (t < EE) ? ei[EE + t] : (t - EE);
    atomicAdd(&deg[d], 1);
}

// single-block two-pass scan: rowptr = exclusive_scan(deg); cursor = rowptr
__global__ void __launch_bounds__(1024) scan_one(
        const int* __restrict__ deg, int* __restrict__ rowptr, int* __restrict__ cursor)
{
    __shared__ int sh[1024];
    const int CH = (NN + 1023) / 1024;   // 49
    int t = threadIdx.x;
    int b0 = t * CH, b1 = min(b0 + CH, NN);
    int s = 0;
    for (int i = b0; i < b1; i++) s += deg[i];
    sh[t] = s;
    __syncthreads();
    int v = s;
    #pragma unroll
    for (int st = 1; st < 1024; st <<= 1) {
        int tmp = (t >= st) ? sh[t - st] : 0;
        __syncthreads();
        sh[t] += tmp;
        __syncthreads();
    }
    int pre = sh[t] - v;                 // exclusive prefix
    for (int i = b0; i < b1; i++) {
        rowptr[i] = pre; cursor[i] = pre;
        pre += deg[i];
    }
    if (t == 0) rowptr[NN] = ET;
}

__global__ void csr_fill(const int* __restrict__ ei, int* __restrict__ cursor,
                         int* __restrict__ col) {
    int t = blockIdx.x * blockDim.x + threadIdx.x;
    if (t >= ET) return;
    int s, d;
    if (t < EE) { s = ei[t]; d = ei[EE + t]; } else { s = d = t - EE; }
    int pos = atomicAdd(&cursor[d], 1);
    col[pos] = s;
}

// ================= projection: xs=X@Ws (FFMA2), a_s = xs·atts, a_d = X·vd ====
__global__ void __launch_bounds__(256) proj_kernel(
        const float* __restrict__ X,
        const float* __restrict__ Ws,
        const float* __restrict__ atts, const float* __restrict__ vd,
        float* __restrict__ xs,
        float* __restrict__ av_s, float* __restrict__ av_d)
{
    __shared__ float Wt[32 * 128];   // 16KB chunk of Ws
    __shared__ float sx[64 * 128];   // 32KB of X rows
    __shared__ float svd[256];
    int w = threadIdx.x >> 5, lane = threadIdx.x & 31;
    int rowBase = blockIdx.x * 64;

    if (threadIdx.x < 256) svd[threadIdx.x] = vd[threadIdx.x];
    for (int i = threadIdx.x; i < 64 * 32; i += 256) {      // float4 granularity
        int r = i >> 5, c = i & 31;
        if (rowBase + r < NN)
            ((float4*)sx)[i] = ((const float4*)(X + (size_t)(rowBase + r) * 128))[c];
    }

    u64 acc01[8], acc23[8];
    u64 z = pk2(0.f, 0.f);
    #pragma unroll
    for (int r = 0; r < 8; r++) { acc01[r] = z; acc23[r] = z; }

    #pragma unroll 1
    for (int kc = 0; kc < 4; kc++) {
        __syncthreads();
        for (int i = threadIdx.x; i < 32 * 32; i += 256)
            ((float4*)Wt)[i] = ((const float4*)(Ws + kc * 32 * 128))[i];
        __syncthreads();
        const float* xr = sx + (w * 8) * 128 + kc * 32;
        #pragma unroll 2
        for (int k4 = 0; k4 < 8; k4++) {
            float4 xv4[8];
            #pragma unroll
            for (int r = 0; r < 8; r++)
                xv4[r] = ((const float4*)(xr + r * 128))[k4];
            #pragma unroll
            for (int kk = 0; kk < 4; kk++) {
                int k = k4 * 4 + kk;
                ulonglong2 wv = ((const ulonglong2*)(Wt + k * 128))[lane];
                #pragma unroll
                for (int r = 0; r < 8; r++) {
                    float xv = (&xv4[r].x)[kk];
                    u64 xx = pk2(xv, xv);
                    acc01[r] = fma2(xx, wv.x, acc01[r]);
                    acc23[r] = fma2(xx, wv.y, acc23[r]);
                }
            }
        }
    }

    #pragma unroll
    for (int r = 0; r < 8; r++) {
        int row = rowBase + w * 8 + r;
        if (row >= NN) continue;
        float4 a;
        unpk2(a.x, a.y, acc01[r]);
        unpk2(a.z, a.w, acc23[r]);
        ((float4*)(xs + (size_t)row * 128))[lane] = a;

        // a_s = xs_row · atts (lanes 0..15 = head0 cols, 16..31 = head1)
        int colb = lane * 4;
        float p = a.x * atts[colb]     + a.y * atts[colb + 1]
                + a.z * atts[colb + 2] + a.w * atts[colb + 3];
        #pragma unroll
        for (int off = 8; off; off >>= 1)
            p += __shfl_down_sync(0xffffffffu, p, off, 16);
        if (lane == 0)  av_s[row * 2 + 0] = p;
        if (lane == 16) av_s[row * 2 + 1] = p;

        // a_d = X_row · vd (both heads, full-warp reduction)
        float4 xv = ((const float4*)(sx + (w * 8 + r) * 128))[lane];
        int kb = lane * 4;
        float pd0 = xv.x * svd[2 * kb + 0] + xv.y * svd[2 * (kb + 1) + 0]
                  + xv.z * svd[2 * (kb + 2) + 0] + xv.w * svd[2 * (kb + 3) + 0];
        float pd1 = xv.x * svd[2 * kb + 1] + xv.y * svd[2 * (kb + 1) + 1]
                  + xv.z * svd[2 * (kb + 2) + 1] + xv.w * svd[2 * (kb + 3) + 1];
        #pragma unroll
        for (int off = 16; off; off >>= 1) {
            pd0 += __shfl_xor_sync(0xffffffffu, pd0, off);
            pd1 += __shfl_xor_sync(0xffffffffu, pd1, off);
        }
        if (lane == 0) {
            av_d[row * 2 + 0] = pd0;
            av_d[row * 2 + 1] = pd1;
        }
    }
}

// ================= fused GAT aggregation: warp per destination node ==========
// softmax WITHOUT max-subtraction (algebraically identical; logits are O(10)).
__device__ __forceinline__ float lrelu(float v) { return v > 0.f ? v : 0.2f * v; }

__global__ void __launch_bounds__(256) gat_agg(
        const int* __restrict__ rowptr, const int* __restrict__ col,
        const float* __restrict__ a_s, const float* __restrict__ a_d,
        const float* __restrict__ xs,  const float* __restrict__ b,
        float* __restrict__ out)
{
    int n = blockIdx.x * 8 + (threadIdx.x >> 5);
    int lane = threadIdx.x & 31;
    if (n >= NN) return;
    int r0 = rowptr[n], r1 = rowptr[n + 1];
    float ad0 = a_d[n * 2], ad1 = a_d[n * 2 + 1];

    // phase 1: denominators
    float d0 = 0.f, d1 = 0.f;
    for (int j = r0 + lane; j < r1; j += 32) {
        int s = col[j];
        d0 += __expf(lrelu(a_s[s * 2]     + ad0));
        d1 += __expf(lrelu(a_s[s * 2 + 1] + ad1));
    }
    #pragma unroll
    for (int off = 16; off; off >>= 1) {
        d0 += __shfl_xor_sync(0xffffffffu, d0, off);
        d1 += __shfl_xor_sync(0xffffffffu, d1, off);
    }
    int h = lane >> 4;                       // lanes 0..15 head0, 16..31 head1
    float adh  = h ? ad1 : ad0;
    float invh = 1.f / (h ? d1 : d0);

    // phase 2: weighted gather, full warp per edge (FFMA2 accumulate)
    u64 acc01 = pk2(0.f, 0.f), acc23 = acc01;
    for (int j = r0; j < r1; j++) {
        int s = col[j];                      // broadcast load
        float wgt = __expf(lrelu(a_s[s * 2 + h] + adh)) * invh;
        u64 ww = pk2(wgt, wgt);
        ulonglong2 v = ((const ulonglong2*)(xs + (size_t)s * 128))[lane];
        acc01 = fma2(ww, v.x, acc01);
        acc23 = fma2(ww, v.y, acc23);
    }
    float4 acc;
    unpk2(acc.x, acc.y, acc01);
    unpk2(acc.z, acc.w, acc23);
    float4 bb = ((const float4*)b)[lane];
    acc.x = fmaxf(acc.x + bb.x, 0.f);
    acc.y = fmaxf(acc.y + bb.y, 0.f);
    acc.z = fmaxf(acc.z + bb.z, 0.f);
    acc.w = fmaxf(acc.w + bb.w, 0.f);
    ((float4*)(out + (size_t)n * 128))[lane] = acc;
}

// ================= fused pooling + final linear (batch is SORTED) ============
__global__ void __launch_bounds__(256) pool_final(
        const float* __restrict__ h, const int* __restrict__ batch,
        const float* __restrict__ Wl, const float* __restrict__ bl,
        float* __restrict__ out)
{
    __shared__ float part[256];
    __shared__ float row[128];
    int g = blockIdx.x;                      // 64 blocks

    // binary search node range [lo, hi) with batch == g
    int a = 0, bnd = NN;
    while (a < bnd) { int m = (a + bnd) >> 1; if (batch[m] < g) a = m + 1; else bnd = m; }
    int lo = a;
    a = lo; bnd = NN;
    while (a < bnd) { int m = (a + bnd) >> 1; if (batch[m] < g + 1) a = m + 1; else bnd = m; }
    int hi = a;

    int c    = threadIdx.x & 127;
    int half = threadIdx.x >> 7;
    float acc = 0.f;
    for (int r = lo + half; r < hi; r += 2)
        acc += h[(size_t)r * 128 + c];
    part[threadIdx.x] = acc;
    __syncthreads();
    if (threadIdx.x < 128) {
        float inv = 1.f / fmaxf((float)(hi - lo), 1.f);
        row[threadIdx.x] = (part[threadIdx.x] + part[threadIdx.x + 128]) * inv;
    }
    __syncthreads();
    if (threadIdx.x < OUTD) {
        float s = bl[threadIdx.x];
        #pragma unroll 16
        for (int j = 0; j < 128; j++)
            s += row[j] * Wl[j * OUTD + threadIdx.x];
        out[g * OUTD + threadIdx.x] = s;
    }
}

// ================= launch =====================================================
extern "C" void kernel_launch(void* const* d_in, const int* in_sizes, int n_in,
                              void* d_out, int out_size)
{
    const float* x     = (const float*)d_in[0];
    const int*   ei    = (const int*)  d_in[1];
    const int*   batch = (const int*)  d_in[2];
    const float* Ws1   = (const float*)d_in[3];
    const float* Wd1   = (const float*)d_in[4];
    const float* as1   = (const float*)d_in[5];
    const float* ad1   = (const float*)d_in[6];
    const float* b1    = (const float*)d_in[7];
    const float* Ws2   = (const float*)d_in[8];
    const float* Wd2   = (const float*)d_in[9];
    const float* as2   = (const float*)d_in[10];
    const float* ad2   = (const float*)d_in[11];
    const float* b2    = (const float*)d_in[12];
    const float* Wl    = (const float*)d_in[13];
    const float* bl    = (const float*)d_in[14];
    float* out = (float*)d_out;

    void *p_xs, *p_as, *p_ad, *p_h, *p_vd1, *p_vd2;
    void *p_deg, *p_rowptr, *p_cursor, *p_col;
    cudaGetSymbolAddress(&p_xs,  g_xs);
    cudaGetSymbolAddress(&p_as,  g_as);
    cudaGetSymbolAddress(&p_ad,  g_ad);
    cudaGetSymbolAddress(&p_h,   g_h);
    cudaGetSymbolAddress(&p_vd1, g_vd1);
    cudaGetSymbolAddress(&p_vd2, g_vd2);
    cudaGetSymbolAddress(&p_deg,    g_deg);
    cudaGetSymbolAddress(&p_rowptr, g_rowptr);
    cudaGetSymbolAddress(&p_cursor, g_cursor);
    cudaGetSymbolAddress(&p_col,    g_col);

    float* xs  = (float*)p_xs;
    float* asv = (float*)p_as;  float* adv = (float*)p_ad;
    float* hbuf= (float*)p_h;
    float* vd1 = (float*)p_vd1; float* vd2 = (float*)p_vd2;
    int* deg    = (int*)p_deg;    int* rowptr = (int*)p_rowptr;
    int* cursor = (int*)p_cursor; int* col    = (int*)p_col;

    const int PROJ_GRID = (NN + 63) / 64;         // 782
    const int AGG_GRID  = (NN + 7) / 8;           // 6250
    const int EDGE_GRID = (ET + 255) / 256;

    // ---- prelude: zero deg + vd1/vd2 ----
    prelude<<<196, 256>>>(Wd1, ad1, vd1, Wd2, ad2, vd2, deg);

    // ---- CSR build (edge index identical for both layers) ----
    csr_hist<<<EDGE_GRID, 256>>>(ei, deg);
    scan_one<<<1, 1024>>>(deg, rowptr, cursor);
    csr_fill<<<EDGE_GRID, 256>>>(ei, cursor, col);

    // ---- layer 1 ----
    proj_kernel<<<PROJ_GRID, 256>>>(x, Ws1, as1, vd1, xs, asv, adv);
    gat_agg<<<AGG_GRID, 256>>>(rowptr, col, asv, adv, xs, b1, hbuf);

    // ---- layer 2 ----
    proj_kernel<<<PROJ_GRID, 256>>>(hbuf, Ws2, as2, vd2, xs, asv, adv);
    gat_agg<<<AGG_GRID, 256>>>(rowptr, col, asv, adv, xs, b2, hbuf);

    // ---- fused pooling + final linear ----
    pool_final<<<GG, 256>>>(hbuf, batch, Wl, bl, out);
}

// round 5
// speedup vs baseline: 3.1146x; 1.0780x over previous
#include <cuda_runtime.h>
#include <cuda_bf16.h>

#define NN   50000
#define EE   800000
#define ET   (EE + NN)        // edges incl. self loops = 850000
#define FD   128
#define HH   2
#define GG   64
#define OUTD 10

typedef unsigned long long u64;

// ---------------- scratch (device globals; no allocation allowed) ----------
__device__ __nv_bfloat16 g_xsb[NN * FD];  // source projection (bf16 for gather)
__device__ float g_as [NN * HH];     // per-node source attention logit
__device__ float g_ad [NN * HH];     // per-node dest attention logit
__device__ float g_h  [NN * FD];     // layer output (fp32)
__device__ float g_vd1 [FD * HH];    // Wd1 @ ad1 (folded dest attention)
__device__ float g_vd2 [FD * HH];    // Wd2 @ ad2
// CSR
__device__ int g_deg   [NN];
__device__ int g_rowptr[NN + 1];
__device__ int g_cursor[NN];
__device__ int g_col   [ET];

// ---------------- f32x2 helpers ---------------------------------------------
__device__ __forceinline__ u64 pk2(float lo, float hi) {
    u64 r; asm("mov.b64 %0, {%1, %2};" : "=l"(r) : "f"(lo), "f"(hi)); return r;
}
__device__ __forceinline__ void unpk2(float& lo, float& hi, u64 v) {
    asm("mov.b64 {%0, %1}, %2;" : "=f"(lo), "=f"(hi) : "l"(v));
}
__device__ __forceinline__ u64 fma2(u64 a, u64 b, u64 c) {
    u64 d; asm("fma.rn.f32x2 %0, %1, %2, %3;" : "=l"(d) : "l"(a), "l"(b), "l"(c));
    return d;
}

// ================= prelude: zero deg + folded dest-attention vectors =========
__global__ void prelude(const float* __restrict__ Wd1, const float* __restrict__ ad1,
                        float* __restrict__ vd1,
                        const float* __restrict__ Wd2, const float* __restrict__ ad2,
                        float* __restrict__ vd2,
                        int* __restrict__ deg)
{
    int i = blockIdx.x * blockDim.x + threadIdx.x;
    for (int j = i; j < NN; j += gridDim.x * blockDim.x) deg[j] = 0;
    if (blockIdx.x < 2 && threadIdx.x < 128) {
        const float* Wd = blockIdx.x ? Wd2 : Wd1;
        const float* ad = blockIdx.x ? ad2 : ad1;
        float*       vd = blockIdx.x ? vd2 : vd1;
        int k = threadIdx.x;
        #pragma unroll
        for (int h = 0; h < HH; h++) {
            float s = 0.f;
            #pragma unroll 16
            for (int c = 0; c < 64; c++)
                s += Wd[k * 128 + h * 64 + c] * ad[h * 64 + c];
            vd[k * 2 + h] = s;
        }
    }
}

// ================= CSR build ==================================================
__global__ void csr_hist(const int* __restrict__ ei, int* __restrict__ deg) {
    int t = blockIdx.x * blockDim.x + threadIdx.x;
    if (t >= ET) return;
    int d = (t < EE) ? __ldg(ei + EE + t) : (t - EE);
    atomicAdd(&deg[d], 1);
}

// single-block two-pass scan: rowptr = exclusive_scan(deg); cursor = rowptr
__global__ void __launch_bounds__(1024) scan_one(
        const int* __restrict__ deg, int* __restrict__ rowptr, int* __restrict__ cursor)
{
    __shared__ int sh[1024];
    const int CH = (NN + 1023) / 1024;   // 49
    int t = threadIdx.x;
    int b0 = t * CH, b1 = min(b0 + CH, NN);
    int s = 0;
    for (int i = b0; i < b1; i++) s += deg[i];
    sh[t] = s;
    __syncthreads();
    int v = s;
    #pragma unroll
    for (int st = 1; st < 1024; st <<= 1) {
        int tmp = (t >= st) ? sh[t - st] : 0;
        __syncthreads();
        sh[t] += tmp;
        __syncthreads();
    }
    int pre = sh[t] - v;                 // exclusive prefix
    for (int i = b0; i < b1; i++) {
        rowptr[i] = pre; cursor[i] = pre;
        pre += deg[i];
    }
    if (t == 0) rowptr[NN] = ET;
}

__global__ void csr_fill(const int* __restrict__ ei, int* __restrict__ cursor,
                         int* __restrict__ col) {
    int t = blockIdx.x * blockDim.x + threadIdx.x;
    if (t >= ET) return;
    int s, d;
    if (t < EE) { s = __ldg(ei + t); d = __ldg(ei + EE + t); } else { s = d = t - EE; }
    int pos = atomicAdd(&cursor[d], 1);
    col[pos] = s;
}

// ================= projection: xsb=bf16(X@Ws), a_s = xs·atts, a_d = X·vd =====
__global__ void __launch_bounds__(256) proj_kernel(
        const float* __restrict__ X,
        const float* __restrict__ Ws,
        const float* __restrict__ atts, const float* __restrict__ vd,
        __nv_bfloat16* __restrict__ xsb,
        float* __restrict__ av_s, float* __restrict__ av_d)
{
    __shared__ float Wt[32 * 128];   // 16KB chunk of Ws
    __shared__ float sx[64 * 128];   // 32KB of X rows
    __shared__ float svd[256];
    int w = threadIdx.x >> 5, lane = threadIdx.x & 31;
    int rowBase = blockIdx.x * 64;

    if (threadIdx.x < 256) svd[threadIdx.x] = vd[threadIdx.x];
    for (int i = threadIdx.x; i < 64 * 32; i += 256) {      // float4 granularity
        int r = i >> 5, c = i & 31;
        if (rowBase + r < NN)
            ((float4*)sx)[i] = ((const float4*)(X + (size_t)(rowBase + r) * 128))[c];
    }

    u64 acc01[8], acc23[8];
    u64 z = pk2(0.f, 0.f);
    #pragma unroll
    for (int r = 0; r < 8; r++) { acc01[r] = z; acc23[r] = z; }

    #pragma unroll 1
    for (int kc = 0; kc < 4; kc++) {
        __syncthreads();
        for (int i = threadIdx.x; i < 32 * 32; i += 256)
            ((float4*)Wt)[i] = ((const float4*)(Ws + kc * 32 * 128))[i];
        __syncthreads();
        const float* xr = sx + (w * 8) * 128 + kc * 32;
        #pragma unroll 2
        for (int k4 = 0; k4 < 8; k4++) {
            float4 xv4[8];
            #pragma unroll
            for (int r = 0; r < 8; r++)
                xv4[r] = ((const float4*)(xr + r * 128))[k4];
            #pragma unroll
            for (int kk = 0; kk < 4; kk++) {
                int k = k4 * 4 + kk;
                ulonglong2 wv = ((const ulonglong2*)(Wt + k * 128))[lane];
                #pragma unroll
                for (int r = 0; r < 8; r++) {
                    float xv = (&xv4[r].x)[kk];
                    u64 xx = pk2(xv, xv);
                    acc01[r] = fma2(xx, wv.x, acc01[r]);
                    acc23[r] = fma2(xx, wv.y, acc23[r]);
                }
            }
        }
    }

    #pragma unroll
    for (int r = 0; r < 8; r++) {
        int row = rowBase + w * 8 + r;
        if (row >= NN) continue;
        float4 a;
        unpk2(a.x, a.y, acc01[r]);
        unpk2(a.z, a.w, acc23[r]);

        // bf16 store for the gather path (cols lane*4 .. lane*4+3)
        __nv_bfloat162 lo = __float22bfloat162_rn(make_float2(a.x, a.y));
        __nv_bfloat162 hi = __float22bfloat162_rn(make_float2(a.z, a.w));
        uint2 st;
        st.x = *(unsigned int*)&lo;
        st.y = *(unsigned int*)&hi;
        ((uint2*)(xsb + (size_t)row * 128))[lane] = st;

        // a_s = xs_row · atts (lanes 0..15 = head0 cols, 16..31 = head1)
        int colb = lane * 4;
        float p = a.x * atts[colb]     + a.y * atts[colb + 1]
                + a.z * atts[colb + 2] + a.w * atts[colb + 3];
        #pragma unroll
        for (int off = 8; off; off >>= 1)
            p += __shfl_down_sync(0xffffffffu, p, off, 16);
        if (lane == 0)  av_s[row * 2 + 0] = p;
        if (lane == 16) av_s[row * 2 + 1] = p;

        // a_d = X_row · vd (both heads, full-warp reduction)
        float4 xv = ((const float4*)(sx + (w * 8 + r) * 128))[lane];
        int kb = lane * 4;
        float pd0 = xv.x * svd[2 * kb + 0] + xv.y * svd[2 * (kb + 1) + 0]
                  + xv.z * svd[2 * (kb + 2) + 0] + xv.w * svd[2 * (kb + 3) + 0];
        float pd1 = xv.x * svd[2 * kb + 1] + xv.y * svd[2 * (kb + 1) + 1]
                  + xv.z * svd[2 * (kb + 2) + 1] + xv.w * svd[2 * (kb + 3) + 1];
        #pragma unroll
        for (int off = 16; off; off >>= 1) {
            pd0 += __shfl_xor_sync(0xffffffffu, pd0, off);
            pd1 += __shfl_xor_sync(0xffffffffu, pd1, off);
        }
        if (lane == 0) {
            av_d[row * 2 + 0] = pd0;
            av_d[row * 2 + 1] = pd1;
        }
    }
}

// ================= fused GAT aggregation: warp per destination node ==========
// Single pass: accumulate sum(w * xs) and sum(w); divide at the end.
// Chunked: 32 edge weights computed in parallel (full MLP), then 32
// independent bf16 gathers (only dependence = 4-deep FMA chain).
__global__ void __launch_bounds__(256) gat_agg(
        const int* __restrict__ rowptr, const int* __restrict__ col,
        const float* __restrict__ a_s, const float* __restrict__ a_d,
        const __nv_bfloat16* __restrict__ xsb, const float* __restrict__ b,
        float* __restrict__ out)
{
    __shared__ int   ss [8][32];
    __shared__ float sw0[8][32];
    __shared__ float sw1[8][32];
    int wid = threadIdx.x >> 5, lane = threadIdx.x & 31;
    int n = blockIdx.x * 8 + wid;
    if (n >= NN) return;
    int r0 = rowptr[n], r1 = rowptr[n + 1];
    int deg = r1 - r0;
    float2 adv = ((const float2*)a_d)[n];
    int h = lane >> 4;                       // lanes 0..15 head0, 16..31 head1

    float acc0 = 0.f, acc1 = 0.f, acc2 = 0.f, acc3 = 0.f;
    float ws0 = 0.f, ws1 = 0.f;

    for (int base = 0; base < deg; base += 32) {
        int e = base + lane;
        int s = n; float w0 = 0.f, w1 = 0.f;
        if (e < deg) {
            s = __ldg(col + r0 + e);
            float2 av = ((const float2*)a_s)[s];
            float l0 = av.x + adv.x; l0 = l0 > 0.f ? l0 : 0.2f * l0;
            float l1 = av.y + adv.y; l1 = l1 > 0.f ? l1 : 0.2f * l1;
            w0 = __expf(l0); w1 = __expf(l1);
            ws0 += w0; ws1 += w1;
        }
        ss [wid][lane] = s;
        sw0[wid][lane] = w0;
        sw1[wid][lane] = w1;
        __syncwarp();
        int cnt = min(32, deg - base);
        const float* swh = h ? sw1[wid] : sw0[wid];
        #pragma unroll 4
        for (int e2 = 0; e2 < cnt; e2++) {
            int   sj = ss[wid][e2];
            float wj = swh[e2];
            uint2 v = ((const uint2*)(xsb + (size_t)sj * 128))[lane];
            float2 f01 = __bfloat1622float2(*(__nv_bfloat162*)&v.x);
            float2 f23 = __bfloat1622float2(*(__nv_bfloat162*)&v.y);
            acc0 += wj * f01.x; acc1 += wj * f01.y;
            acc2 += wj * f23.x; acc3 += wj * f23.y;
        }
        __syncwarp();
    }

    // warp-reduce weight sums, pick per-head inverse
    #pragma unroll
    for (int off = 16; off; off >>= 1) {
        ws0 += __shfl_xor_sync(0xffffffffu, ws0, off);
        ws1 += __shfl_xor_sync(0xffffffffu, ws1, off);
    }
    float inv = 1.f / (h ? ws1 : ws0);

    float4 bb = ((const float4*)b)[lane];
    float4 o;
    o.x = fmaxf(acc0 * inv + bb.x, 0.f);
    o.y = fmaxf(acc1 * inv + bb.y, 0.f);
    o.z = fmaxf(acc2 * inv + bb.z, 0.f);
    o.w = fmaxf(acc3 * inv + bb.w, 0.f);
    ((float4*)(out + (size_t)n * 128))[lane] = o;
}

// ================= fused pooling + final linear (batch is SORTED) ============
__global__ void __launch_bounds__(256) pool_final(
        const float* __restrict__ h, const int* __restrict__ batch,
        const float* __restrict__ Wl, const float* __restrict__ bl,
        float* __restrict__ out)
{
    __shared__ float part[256];
    __shared__ float row[128];
    int g = blockIdx.x;                      // 64 blocks

    // binary search node range [lo, hi) with batch == g
    int a = 0, bnd = NN;
    while (a < bnd) { int m = (a + bnd) >> 1; if (batch[m] < g) a = m + 1; else bnd = m; }
    int lo = a;
    a = lo; bnd = NN;
    while (a < bnd) { int m = (a + bnd) >> 1; if (batch[m] < g + 1) a = m + 1; else bnd = m; }
    int hi = a;

    int c    = threadIdx.x & 127;
    int half = threadIdx.x >> 7;
    float acc = 0.f;
    for (int r = lo + half; r < hi; r += 2)
        acc += h[(size_t)r * 128 + c];
    part[threadIdx.x] = acc;
    __syncthreads();
    if (threadIdx.x < 128) {
        float inv = 1.f / fmaxf((float)(hi - lo), 1.f);
        row[threadIdx.x] = (part[threadIdx.x] + part[threadIdx.x + 128]) * inv;
    }
    __syncthreads();
    if (threadIdx.x < OUTD) {
        float s = bl[threadIdx.x];
        #pragma unroll 16
        for (int j = 0; j < 128; j++)
            s += row[j] * Wl[j * OUTD + threadIdx.x];
        out[g * OUTD + threadIdx.x] = s;
    }
}

// ================= launch =====================================================
extern "C" void kernel_launch(void* const* d_in, const int* in_sizes, int n_in,
                              void* d_out, int out_size)
{
    const float* x     = (const float*)d_in[0];
    const int*   ei    = (const int*)  d_in[1];
    const int*   batch = (const int*)  d_in[2];
    const float* Ws1   = (const float*)d_in[3];
    const float* Wd1   = (const float*)d_in[4];
    const float* as1   = (const float*)d_in[5];
    const float* ad1   = (const float*)d_in[6];
    const float* b1    = (const float*)d_in[7];
    const float* Ws2   = (const float*)d_in[8];
    const float* Wd2   = (const float*)d_in[9];
    const float* as2   = (const float*)d_in[10];
    const float* ad2   = (const float*)d_in[11];
    const float* b2    = (const float*)d_in[12];
    const float* Wl    = (const float*)d_in[13];
    const float* bl    = (const float*)d_in[14];
    float* out = (float*)d_out;

    void *p_xsb, *p_as, *p_ad, *p_h, *p_vd1, *p_vd2;
    void *p_deg, *p_rowptr, *p_cursor, *p_col;
    cudaGetSymbolAddress(&p_xsb, g_xsb);
    cudaGetSymbolAddress(&p_as,  g_as);
    cudaGetSymbolAddress(&p_ad,  g_ad);
    cudaGetSymbolAddress(&p_h,   g_h);
    cudaGetSymbolAddress(&p_vd1, g_vd1);
    cudaGetSymbolAddress(&p_vd2, g_vd2);
    cudaGetSymbolAddress(&p_deg,    g_deg);
    cudaGetSymbolAddress(&p_rowptr, g_rowptr);
    cudaGetSymbolAddress(&p_cursor, g_cursor);
    cudaGetSymbolAddress(&p_col,    g_col);

    __nv_bfloat16* xsb = (__nv_bfloat16*)p_xsb;
    float* asv = (float*)p_as;  float* adv = (float*)p_ad;
    float* hbuf= (float*)p_h;
    float* vd1 = (float*)p_vd1; float* vd2 = (float*)p_vd2;
    int* deg    = (int*)p_deg;    int* rowptr = (int*)p_rowptr;
    int* cursor = (int*)p_cursor; int* col    = (int*)p_col;

    const int PROJ_GRID = (NN + 63) / 64;         // 782
    const int AGG_GRID  = (NN + 7) / 8;           // 6250
    const int EDGE_GRID = (ET + 255) / 256;

    // ---- prelude: zero deg + vd1/vd2 ----
    prelude<<<196, 256>>>(Wd1, ad1, vd1, Wd2, ad2, vd2, deg);

    // ---- CSR build (edge index identical for both layers) ----
    csr_hist<<<EDGE_GRID, 256>>>(ei, deg);
    scan_one<<<1, 1024>>>(deg, rowptr, cursor);
    csr_fill<<<EDGE_GRID, 256>>>(ei, cursor, col);

    // ---- layer 1 ----
    proj_kernel<<<PROJ_GRID, 256>>>(x, Ws1, as1, vd1, xsb, asv, adv);
    gat_agg<<<AGG_GRID, 256>>>(rowptr, col, asv, adv, xsb, b1, hbuf);

    // ---- layer 2 ----
    proj_kernel<<<PROJ_GRID, 256>>>(hbuf, Ws2, as2, vd2, xsb, asv, adv);
    gat_agg<<<AGG_GRID, 256>>>(rowptr, col, asv, adv, xsb, b2, hbuf);

    // ---- fused pooling + final linear ----
    pool_final<<<GG, 256>>>(hbuf, batch, Wl, bl, out);
}

// round 7
// speedup vs baseline: 3.3985x; 1.0912x over previous
#include <cuda_runtime.h>
#include <cuda_bf16.h>
#include <cstdint>

#define NN   50000
#define EE   800000
#define ET   (EE + NN)        // edges incl. self loops = 850000
#define FD   128
#define HH   2
#define GG   64
#define OUTD 10
#define NTILE ((NN + 127) / 128)   // 391 M-tiles

// ---------------- scratch (device globals; no allocation allowed) ----------
__device__ __nv_bfloat16 g_xsb[NN * FD];  // source projection (bf16 for gather)
__device__ float g_as [NN * HH];     // per-node source attention logit
__device__ float g_ad [NN * HH];     // per-node dest attention logit
__device__ float g_h  [NN * FD];     // layer output (fp32)
__device__ float g_vd1 [FD * HH];    // Wd1 @ ad1 (folded dest attention)
__device__ float g_vd2 [FD * HH];    // Wd2 @ ad2
// W^T bf16 hi/lo (row-major [n][k], 128x128 bf16 = 32KB each)
__device__ __nv_bfloat16 g_wh1[FD * FD];
__device__ __nv_bfloat16 g_wl1[FD * FD];
__device__ __nv_bfloat16 g_wh2[FD * FD];
__device__ __nv_bfloat16 g_wl2[FD * FD];
// CSR
__device__ int g_deg   [NN];
__device__ int g_rowptr[NN + 1];
__device__ int g_cursor[NN];
__device__ int g_col   [ET];

// ================= prelude: zero deg + vd vectors =============================
__global__ void prelude(const float* __restrict__ Wd1, const float* __restrict__ ad1,
                        float* __restrict__ vd1,
                        const float* __restrict__ Wd2, const float* __restrict__ ad2,
                        float* __restrict__ vd2,
                        int* __restrict__ deg)
{
    int i = blockIdx.x * blockDim.x + threadIdx.x;
    for (int j = i; j < NN; j += gridDim.x * blockDim.x) deg[j] = 0;
    if (blockIdx.x < 2 && threadIdx.x < 128) {
        const float* Wd = blockIdx.x ? Wd2 : Wd1;
        const float* ad = blockIdx.x ? ad2 : ad1;
        float*       vd = blockIdx.x ? vd2 : vd1;
        int k = threadIdx.x;
        #pragma unroll
        for (int h = 0; h < HH; h++) {
            float s = 0.f;
            #pragma unroll 16
            for (int c = 0; c < 64; c++)
                s += Wd[k * 128 + h * 64 + c] * ad[h * 64 + c];
            vd[k * 2 + h] = s;
        }
    }
}

// ========== W -> transposed bf16 hi/lo: WT[n][k] = W[k][n], hi + residual ====
__global__ void wprep(const float* __restrict__ W1, const float* __restrict__ W2,
                      __nv_bfloat16* __restrict__ wh1, __nv_bfloat16* __restrict__ wl1,
                      __nv_bfloat16* __restrict__ wh2, __nv_bfloat16* __restrict__ wl2)
{
    const float* W = blockIdx.x ? W2 : W1;
    __nv_bfloat16* wh = blockIdx.x ? wh2 : wh1;
    __nv_bfloat16* wl = blockIdx.x ? wl2 : wl1;
    for (int idx = threadIdx.x; idx < FD * FD; idx += blockDim.x) {
        int n = idx >> 7, k = idx & 127;
        float x = W[k * 128 + n];
        __nv_bfloat16 h = __float2bfloat16_rn(x);
        __nv_bfloat16 l = __float2bfloat16_rn(x - __bfloat162float(h));
        wh[n * 128 + k] = h;
        wl[n * 128 + k] = l;
    }
}

// ================= CSR build ==================================================
__global__ void csr_hist(const int* __restrict__ ei, int* __restrict__ deg) {
    int t = blockIdx.x * blockDim.x + threadIdx.x;
    if (t >= ET) return;
    int d = (t < EE) ? __ldg(ei + EE + t) : (t - EE);
    atomicAdd(&deg[d], 1);
}

__global__ void __launch_bounds__(1024) scan_one(
        const int* __restrict__ deg, int* __restrict__ rowptr, int* __restrict__ cursor)
{
    __shared__ int sh[1024];
    const int CH = (NN + 1023) / 1024;   // 49
    int t = threadIdx.x;
    int b0 = t * CH, b1 = min(b0 + CH, NN);
    int s = 0;
    for (int i = b0; i < b1; i++) s += deg[i];
    sh[t] = s;
    __syncthreads();
    int v = s;
    #pragma unroll
    for (int st = 1; st < 1024; st <<= 1) {
        int tmp = (t >= st) ? sh[t - st] : 0;
        __syncthreads();
        sh[t] += tmp;
        __syncthreads();
    }
    int pre = sh[t] - v;
    for (int i = b0; i < b1; i++) {
        rowptr[i] = pre; cursor[i] = pre;
        pre += deg[i];
    }
    if (t == 0) rowptr[NN] = ET;
}

__global__ void csr_fill(const int* __restrict__ ei, int* __restrict__ cursor,
                         int* __restrict__ col) {
    int t = blockIdx.x * blockDim.x + threadIdx.x;
    if (t >= ET) return;
    int s, d;
    if (t < EE) { s = __ldg(ei + t); d = __ldg(ei + EE + t); } else { s = d = t - EE; }
    int pos = atomicAdd(&cursor[d], 1);
    col[pos] = s;
}

// ================= tensor-core projection (mma.sync bf16 HMMA) ===============
// D[128 x 128] = Xb @ Wh^T + Xb @ Wl^T  (fp32 accum in registers)
// Epilogue: xsb = bf16(D), a_s = D.atts; conversion phase computes a_d = X.vd.
#define XB_STRIDE 272                 // bytes per padded smem row (136 bf16)
#define SMX  0
#define SWH  34816
#define SWL  69632
#define SATT 104448                   // 128 f32
#define SVD  104960                   // 256 f32
#define SM_DYN 105984

__device__ __forceinline__ void mma16816(float* c, uint32_t a0, uint32_t a1,
                                         uint32_t a2, uint32_t a3,
                                         uint32_t b0, uint32_t b1) {
    asm volatile(
        "mma.sync.aligned.m16n8k16.row.col.f32.bf16.bf16.f32 "
        "{%0,%1,%2,%3}, {%4,%5,%6,%7}, {%8,%9}, {%0,%1,%2,%3};"
        : "+f"(c[0]), "+f"(c[1]), "+f"(c[2]), "+f"(c[3])
        : "r"(a0), "r"(a1), "r"(a2), "r"(a3), "r"(b0), "r"(b1));
}

__global__ void __launch_bounds__(256)
proj_tc(const float* __restrict__ X,
        const __nv_bfloat16* __restrict__ wh, const __nv_bfloat16* __restrict__ wl,
        const float* __restrict__ atts, const float* __restrict__ vd,
        __nv_bfloat16* __restrict__ xsb,
        float* __restrict__ av_s, float* __restrict__ av_d)
{
    extern __shared__ char smem[];
    int tid = threadIdx.x, wid = tid >> 5, lane = tid & 31;
    int base = blockIdx.x * 128;

    if (tid < 128) ((float*)(smem + SATT))[tid] = atts[tid];
    if (tid < 256) ((float*)(smem + SVD))[tid]  = vd[tid];

    // W images -> smem (padded stride)
    for (int i = tid; i < 2048; i += 256) {      // 2048 uint4 per matrix
        int r = i >> 4, c16 = i & 15;
        *(uint4*)(smem + SWH + r * XB_STRIDE + c16 * 16) = ((const uint4*)wh)[i];
        *(uint4*)(smem + SWL + r * XB_STRIDE + c16 * 16) = ((const uint4*)wl)[i];
    }

    // X fp32 -> bf16 smem tile (+ a_d = X.vd). warp w handles rows w+8k.
    {
        const float2* svd2 = (const float2*)(smem + SVD);
        #pragma unroll 1
        for (int k = 0; k < 16; k++) {
            int r = wid + 8 * k;
            int row = base + r;
            float4 xv = make_float4(0.f, 0.f, 0.f, 0.f);
            if (row < NN)
                xv = ((const float4*)(X + (size_t)row * 128))[lane];
            __nv_bfloat162 p0 = __float22bfloat162_rn(make_float2(xv.x, xv.y));
            __nv_bfloat162 p1 = __float22bfloat162_rn(make_float2(xv.z, xv.w));
            uint2 st; st.x = *(unsigned*)&p0; st.y = *(unsigned*)&p1;
            *(uint2*)(smem + SMX + r * XB_STRIDE + lane * 8) = st;
            // a_d partial over this lane's 4 cols
            float2 v0 = svd2[lane * 4 + 0], v1 = svd2[lane * 4 + 1];
            float2 v2 = svd2[lane * 4 + 2], v3 = svd2[lane * 4 + 3];
            float pd0 = xv.x * v0.x + xv.y * v1.x + xv.z * v2.x + xv.w * v3.x;
            float pd1 = xv.x * v0.y + xv.y * v1.y + xv.z * v2.y + xv.w * v3.y;
            #pragma unroll
            for (int o = 16; o; o >>= 1) {
                pd0 += __shfl_xor_sync(0xffffffffu, pd0, o);
                pd1 += __shfl_xor_sync(0xffffffffu, pd1, o);
            }
            if (lane == 0 && row < NN)
                ((float2*)av_d)[row] = make_float2(pd0, pd1);
        }
    }
    __syncthreads();

    // MMA: warp wid owns rows [wid*16, wid*16+16)
    float acc[16][4];
    #pragma unroll
    for (int nt = 0; nt < 16; nt++)
        #pragma unroll
        for (int q = 0; q < 4; q++) acc[nt][q] = 0.f;

    int gid = lane >> 2, tig = lane & 3;
    int rowA = wid * 16 + gid;
    const char* sx = smem + SMX;

    #pragma unroll 1
    for (int pass = 0; pass < 2; pass++) {
        const char* sw = smem + (pass ? SWL : SWH);
        #pragma unroll 1
        for (int ks = 0; ks < 8; ks++) {
            int k0 = ks * 16;
            uint32_t a0 = *(const uint32_t*)(sx + rowA * XB_STRIDE + (k0 + 2 * tig) * 2);
            uint32_t a1 = *(const uint32_t*)(sx + (rowA + 8) * XB_STRIDE + (k0 + 2 * tig) * 2);
            uint32_t a2 = *(const uint32_t*)(sx + rowA * XB_STRIDE + (k0 + 8 + 2 * tig) * 2);
            uint32_t a3 = *(const uint32_t*)(sx + (rowA + 8) * XB_STRIDE + (k0 + 8 + 2 * tig) * 2);
            #pragma unroll
            for (int nt = 0; nt < 16; nt++) {
                const char* wr = sw + (nt * 8 + gid) * XB_STRIDE;
                uint32_t b0 = *(const uint32_t*)(wr + (k0 + 2 * tig) * 2);
                uint32_t b1 = *(const uint32_t*)(wr + (k0 + 8 + 2 * tig) * 2);
                mma16816(acc[nt], a0, a1, a2, a3, b0, b1);
            }
        }
    }

    // epilogue: xsb stores + a_s head dots
    {
        const float* sa = (const float*)(smem + SATT);
        int row0 = base + wid * 16 + gid;
        int row1 = row0 + 8;
        float p0h0 = 0.f, p0h1 = 0.f, p1h0 = 0.f, p1h1 = 0.f;
        #pragma unroll
        for (int nt = 0; nt < 16; nt++) {
            int col = nt * 8 + 2 * tig;
            float s0 = sa[col], s1 = sa[col + 1];
            float d00 = acc[nt][0] * s0 + acc[nt][1] * s1;
            float d01 = acc[nt][2] * s0 + acc[nt][3] * s1;
            if (nt < 8) { p0h0 += d00; p1h0 += d01; }
            else        { p0h1 += d00; p1h1 += d01; }
            __nv_bfloat162 q0 = __float22bfloat162_rn(make_float2(acc[nt][0], acc[nt][1]));
            __nv_bfloat162 q1 = __float22bfloat162_rn(make_float2(acc[nt][2], acc[nt][3]));
            if (row0 < NN) *(unsigned*)(xsb + (size_t)row0 * 128 + col) = *(unsigned*)&q0;
            if (row1 < NN) *(unsigned*)(xsb + (size_t)row1 * 128 + col) = *(unsigned*)&q1;
        }
        #pragma unroll
        for (int o = 1; o <= 2; o <<= 1) {
            p0h0 += __shfl_xor_sync(0xffffffffu, p0h0, o);
            p0h1 += __shfl_xor_sync(0xffffffffu, p0h1, o);
            p1h0 += __shfl_xor_sync(0xffffffffu, p1h0, o);
            p1h1 += __shfl_xor_sync(0xffffffffu, p1h1, o);
        }
        if (tig == 0) {
            if (row0 < NN) ((float2*)av_s)[row0] = make_float2(p0h0, p0h1);
            if (row1 < NN) ((float2*)av_s)[row1] = make_float2(p1h0, p1h1);
        }
    }
}

// ================= fused GAT aggregation: warp per destination node ==========
__global__ void __launch_bounds__(256) gat_agg(
        const int* __restrict__ rowptr, const int* __restrict__ col,
        const float* __restrict__ a_s, const float* __restrict__ a_d,
        const __nv_bfloat16* __restrict__ xsb, const float* __restrict__ b,
        float* __restrict__ out)
{
    __shared__ int   ss [8][32];
    __shared__ float sw0[8][32];
    __shared__ float sw1[8][32];
    int wid = threadIdx.x >> 5, lane = threadIdx.x & 31;
    int n = blockIdx.x * 8 + wid;
    if (n >= NN) return;
    int r0 = rowptr[n], r1 = rowptr[n + 1];
    int deg = r1 - r0;
    float2 adv = ((const float2*)a_d)[n];
    int h = lane >> 4;

    float acc0 = 0.f, acc1 = 0.f, acc2 = 0.f, acc3 = 0.f;
    float ws0 = 0.f, ws1 = 0.f;

    for (int base = 0; base < deg; base += 32) {
        int e = base + lane;
        int s = n; float w0 = 0.f, w1 = 0.f;
        if (e < deg) {
            s = __ldg(col + r0 + e);
            float2 av = ((const float2*)a_s)[s];
            float l0 = av.x + adv.x; l0 = l0 > 0.f ? l0 : 0.2f * l0;
            float l1 = av.y + adv.y; l1 = l1 > 0.f ? l1 : 0.2f * l1;
            w0 = __expf(l0); w1 = __expf(l1);
            ws0 += w0; ws1 += w1;
        }
        ss [wid][lane] = s;
        sw0[wid][lane] = w0;
        sw1[wid][lane] = w1;
        __syncwarp();
        int cnt = min(32, deg - base);
        const float* swh = h ? sw1[wid] : sw0[wid];
        #pragma unroll 8
        for (int e2 = 0; e2 < cnt; e2++) {
            int   sj = ss[wid][e2];
            float wj = swh[e2];
            uint2 v = ((const uint2*)(xsb + (size_t)sj * 128))[lane];
            float2 f01 = __bfloat1622float2(*(__nv_bfloat162*)&v.x);
            float2 f23 = __bfloat1622float2(*(__nv_bfloat162*)&v.y);
            acc0 += wj * f01.x; acc1 += wj * f01.y;
            acc2 += wj * f23.x; acc3 += wj * f23.y;
        }
        __syncwarp();
    }

    #pragma unroll
    for (int off = 16; off; off >>= 1) {
        ws0 += __shfl_xor_sync(0xffffffffu, ws0, off);
        ws1 += __shfl_xor_sync(0xffffffffu, ws1, off);
    }
    float inv = 1.f / (h ? ws1 : ws0);

    float4 bb = ((const float4*)b)[lane];
    float4 o;
    o.x = fmaxf(acc0 * inv + bb.x, 0.f);
    o.y = fmaxf(acc1 * inv + bb.y, 0.f);
    o.z = fmaxf(acc2 * inv + bb.z, 0.f);
    o.w = fmaxf(acc3 * inv + bb.w, 0.f);
    ((float4*)(out + (size_t)n * 128))[lane] = o;
}

// ================= fused pooling + final linear (batch is SORTED) ============
__global__ void __launch_bounds__(256) pool_final(
        const float* __restrict__ h, const int* __restrict__ batch,
        const float* __restrict__ Wl, const float* __restrict__ bl,
        float* __restrict__ out)
{
    __shared__ float part[256];
    __shared__ float row[128];
    int g = blockIdx.x;

    int a = 0, bnd = NN;
    while (a < bnd) { int m = (a + bnd) >> 1; if (batch[m] < g) a = m + 1; else bnd = m; }
    int lo = a;
    a = lo; bnd = NN;
    while (a < bnd) { int m = (a + bnd) >> 1; if (batch[m] < g + 1) a = m + 1; else bnd = m; }
    int hi = a;

    int c    = threadIdx.x & 127;
    int half = threadIdx.x >> 7;
    float acc = 0.f;
    for (int r = lo + half; r < hi; r += 2)
        acc += h[(size_t)r * 128 + c];
    part[threadIdx.x] = acc;
    __syncthreads();
    if (threadIdx.x < 128) {
        float inv = 1.f / fmaxf((float)(hi - lo), 1.f);
        row[threadIdx.x] = (part[threadIdx.x] + part[threadIdx.x + 128]) * inv;
    }
    __syncthreads();
    if (threadIdx.x < OUTD) {
        float s = bl[threadIdx.x];
        #pragma unroll 16
        for (int j = 0; j < 128; j++)
            s += row[j] * Wl[j * OUTD + threadIdx.x];
        out[g * OUTD + threadIdx.x] = s;
    }
}

// ================= launch =====================================================
extern "C" void kernel_launch(void* const* d_in, const int* in_sizes, int n_in,
                              void* d_out, int out_size)
{
    const float* x     = (const float*)d_in[0];
    const int*   ei    = (const int*)  d_in[1];
    const int*   batch = (const int*)  d_in[2];
    const float* Ws1   = (const float*)d_in[3];
    const float* Wd1   = (const float*)d_in[4];
    const float* as1   = (const float*)d_in[5];
    const float* ad1   = (const float*)d_in[6];
    const float* b1    = (const float*)d_in[7];
    const float* Ws2   = (const float*)d_in[8];
    const float* Wd2   = (const float*)d_in[9];
    const float* as2   = (const float*)d_in[10];
    const float* ad2   = (const float*)d_in[11];
    const float* b2    = (const float*)d_in[12];
    const float* Wl    = (const float*)d_in[13];
    const float* bl    = (const float*)d_in[14];
    float* out = (float*)d_out;

    void *p_xsb, *p_as, *p_ad, *p_h, *p_vd1, *p_vd2;
    void *p_wh1, *p_wl1, *p_wh2, *p_wl2;
    void *p_deg, *p_rowptr, *p_cursor, *p_col;
    cudaGetSymbolAddress(&p_xsb, g_xsb);
    cudaGetSymbolAddress(&p_as,  g_as);
    cudaGetSymbolAddress(&p_ad,  g_ad);
    cudaGetSymbolAddress(&p_h,   g_h);
    cudaGetSymbolAddress(&p_vd1, g_vd1);
    cudaGetSymbolAddress(&p_vd2, g_vd2);
    cudaGetSymbolAddress(&p_wh1, g_wh1);
    cudaGetSymbolAddress(&p_wl1, g_wl1);
    cudaGetSymbolAddress(&p_wh2, g_wh2);
    cudaGetSymbolAddress(&p_wl2, g_wl2);
    cudaGetSymbolAddress(&p_deg,    g_deg);
    cudaGetSymbolAddress(&p_rowptr, g_rowptr);
    cudaGetSymbolAddress(&p_cursor, g_cursor);
    cudaGetSymbolAddress(&p_col,    g_col);

    __nv_bfloat16* xsb = (__nv_bfloat16*)p_xsb;
    float* asv = (float*)p_as;  float* adv = (float*)p_ad;
    float* hbuf= (float*)p_h;
    float* vd1 = (float*)p_vd1; float* vd2 = (float*)p_vd2;
    __nv_bfloat16* wh1 = (__nv_bfloat16*)p_wh1;
    __nv_bfloat16* wl1 = (__nv_bfloat16*)p_wl1;
    __nv_bfloat16* wh2 = (__nv_bfloat16*)p_wh2;
    __nv_bfloat16* wl2 = (__nv_bfloat16*)p_wl2;
    int* deg    = (int*)p_deg;    int* rowptr = (int*)p_rowptr;
    int* cursor = (int*)p_cursor; int* col    = (int*)p_col;

    const int AGG_GRID  = (NN + 7) / 8;
    const int EDGE_GRID = (ET + 255) / 256;

    cudaFuncSetAttribute(proj_tc, cudaFuncAttributeMaxDynamicSharedMemorySize, SM_DYN);

    prelude<<<196, 256>>>(Wd1, ad1, vd1, Wd2, ad2, vd2, deg);
    wprep<<<2, 256>>>(Ws1, Ws2, wh1, wl1, wh2, wl2);

    csr_hist<<<EDGE_GRID, 256>>>(ei, deg);
    scan_one<<<1, 1024>>>(deg, rowptr, cursor);
    csr_fill<<<EDGE_GRID, 256>>>(ei, cursor, col);

    proj_tc<<<NTILE, 256, SM_DYN>>>(x, wh1, wl1, as1, vd1, xsb, asv, adv);
    gat_agg<<<AGG_GRID, 256>>>(rowptr, col, asv, adv, xsb, b1, hbuf);

    proj_tc<<<NTILE, 256, SM_DYN>>>(hbuf, wh2, wl2, as2, vd2, xsb, asv, adv);
    gat_agg<<<AGG_GRID, 256>>>(rowptr, col, asv, adv, xsb, b2, hbuf);

    pool_final<<<GG, 256>>>(hbuf, batch, Wl, bl, out);
}

// round 8
// speedup vs baseline: 4.3463x; 1.2789x over previous
#include <cuda_runtime.h>
#include <cuda_bf16.h>
#include <cstdint>

#define NN   50000
#define EE   800000
#define ET   (EE + NN)        // edges incl. self loops = 850000
#define FD   128
#define HH   2
#define GG   64
#define OUTD 10
#define NTILE ((NN + 127) / 128)   // 391 M-tiles
#define SBLK ((NN + 1023) / 1024)  // 49 scan blocks

// ---------------- scratch (device globals; no allocation allowed) ----------
__device__ __nv_bfloat16 g_xsb[NN * FD];  // source projection (bf16 for gather)
__device__ float g_as [NN * HH];     // per-node source attention logit
__device__ float g_ad [NN * HH];     // per-node dest attention logit
__device__ float g_h  [NN * FD];     // layer output (fp32)
__device__ float g_vd1 [FD * HH];    // Wd1 @ ad1 (folded dest attention)
__device__ float g_vd2 [FD * HH];    // Wd2 @ ad2
// W^T bf16 hi/lo (row-major [n][k], 128x128 bf16 = 32KB each)
__device__ __nv_bfloat16 g_wh1[FD * FD];
__device__ __nv_bfloat16 g_wl1[FD * FD];
__device__ __nv_bfloat16 g_wh2[FD * FD];
__device__ __nv_bfloat16 g_wl2[FD * FD];
// CSR
__device__ int g_deg   [NN];
__device__ int g_rowptr[NN + 1];
__device__ int g_cursor[NN];
__device__ int g_col   [ET];
__device__ int g_bsum  [SBLK];

// ================= prelude: zero deg + vd vectors =============================
__global__ void prelude(const float* __restrict__ Wd1, const float* __restrict__ ad1,
                        float* __restrict__ vd1,
                        const float* __restrict__ Wd2, const float* __restrict__ ad2,
                        float* __restrict__ vd2,
                        int* __restrict__ deg)
{
    int i = blockIdx.x * blockDim.x + threadIdx.x;
    for (int j = i; j < NN; j += gridDim.x * blockDim.x) deg[j] = 0;
    if (blockIdx.x < 2 && threadIdx.x < 128) {
        const float* Wd = blockIdx.x ? Wd2 : Wd1;
        const float* ad = blockIdx.x ? ad2 : ad1;
        float*       vd = blockIdx.x ? vd2 : vd1;
        int k = threadIdx.x;
        #pragma unroll
        for (int h = 0; h < HH; h++) {
            float s = 0.f;
            #pragma unroll 16
            for (int c = 0; c < 64; c++)
                s += Wd[k * 128 + h * 64 + c] * ad[h * 64 + c];
            vd[k * 2 + h] = s;
        }
    }
}

// ========== W -> transposed bf16 hi/lo: WT[n][k] = W[k][n], hi + residual ====
__global__ void wprep(const float* __restrict__ W1, const float* __restrict__ W2,
                      __nv_bfloat16* __restrict__ wh1, __nv_bfloat16* __restrict__ wl1,
                      __nv_bfloat16* __restrict__ wh2, __nv_bfloat16* __restrict__ wl2)
{
    const float* W = blockIdx.x ? W2 : W1;
    __nv_bfloat16* wh = blockIdx.x ? wh2 : wh1;
    __nv_bfloat16* wl = blockIdx.x ? wl2 : wl1;
    for (int idx = threadIdx.x; idx < FD * FD; idx += blockDim.x) {
        int n = idx >> 7, k = idx & 127;
        float x = W[k * 128 + n];
        __nv_bfloat16 h = __float2bfloat16_rn(x);
        __nv_bfloat16 l = __float2bfloat16_rn(x - __bfloat162float(h));
        wh[n * 128 + k] = h;
        wl[n * 128 + k] = l;
    }
}

// ================= CSR build ==================================================
__global__ void csr_hist(const int* __restrict__ ei, int* __restrict__ deg) {
    int t = blockIdx.x * blockDim.x + threadIdx.x;
    if (t >= ET) return;
    int d = (t < EE) ? __ldg(ei + EE + t) : (t - EE);
    atomicAdd(&deg[d], 1);
}

__global__ void __launch_bounds__(1024) scan_block(
        const int* __restrict__ deg, int* __restrict__ rowptr, int* __restrict__ bsum)
{
    __shared__ int sh[1024];
    int i = blockIdx.x * 1024 + threadIdx.x;
    int v = (i < NN) ? deg[i] : 0;
    sh[threadIdx.x] = v;
    __syncthreads();
    #pragma unroll
    for (int s = 1; s < 1024; s <<= 1) {
        int t = (threadIdx.x >= s) ? sh[threadIdx.x - s] : 0;
        __syncthreads();
        sh[threadIdx.x] += t;
        __syncthreads();
    }
    if (i < NN) rowptr[i] = sh[threadIdx.x] - v;     // exclusive within block
    if (threadIdx.x == 1023) bsum[blockIdx.x] = sh[1023];
}

__global__ void scan_sums(int* __restrict__ bsum) {
    __shared__ int sh[64];
    int tid = threadIdx.x;
    int v = (tid < SBLK) ? bsum[tid] : 0;
    sh[tid] = v;
    __syncthreads();
    #pragma unroll
    for (int s = 1; s < 64; s <<= 1) {
        int t = (tid >= s) ? sh[tid - s] : 0;
        __syncthreads();
        sh[tid] += t;
        __syncthreads();
    }
    if (tid < SBLK) bsum[tid] = sh[tid] - v;          // exclusive
}

__global__ void csr_finalize(const int* __restrict__ bsum, int* __restrict__ rowptr,
                             int* __restrict__ cursor) {
    int i = blockIdx.x * blockDim.x + threadIdx.x;
    if (i < NN) {
        int v = rowptr[i] + bsum[i >> 10];
        rowptr[i] = v;
        cursor[i] = v;
    }
    if (i == 0) rowptr[NN] = ET;
}

__global__ void csr_fill(const int* __restrict__ ei, int* __restrict__ cursor,
                         int* __restrict__ col) {
    int t = blockIdx.x * blockDim.x + threadIdx.x;
    if (t >= ET) return;
    int s, d;
    if (t < EE) { s = __ldg(ei + t); d = __ldg(ei + EE + t); } else { s = d = t - EE; }
    int pos = atomicAdd(&cursor[d], 1);
    col[pos] = s;
}

// ================= tensor-core projection (mma.sync bf16 HMMA) ===============
#define XB_STRIDE 272                 // bytes per padded smem row (136 bf16)
#define SMX  0
#define SWH  34816
#define SWL  69632
#define SATT 104448                   // 128 f32
#define SVD  104960                   // 256 f32
#define SM_DYN 105984

__device__ __forceinline__ void mma16816(float* c, uint32_t a0, uint32_t a1,
                                         uint32_t a2, uint32_t a3,
                                         uint32_t b0, uint32_t b1) {
    asm volatile(
        "mma.sync.aligned.m16n8k16.row.col.f32.bf16.bf16.f32 "
        "{%0,%1,%2,%3}, {%4,%5,%6,%7}, {%8,%9}, {%0,%1,%2,%3};"
        : "+f"(c[0]), "+f"(c[1]), "+f"(c[2]), "+f"(c[3])
        : "r"(a0), "r"(a1), "r"(a2), "r"(a3), "r"(b0), "r"(b1));
}

__global__ void __launch_bounds__(256)
proj_tc(const float* __restrict__ X,
        const __nv_bfloat16* __restrict__ wh, const __nv_bfloat16* __restrict__ wl,
        const float* __restrict__ atts, const float* __restrict__ vd,
        __nv_bfloat16* __restrict__ xsb,
        float* __restrict__ av_s, float* __restrict__ av_d)
{
    extern __shared__ char smem[];
    int tid = threadIdx.x, wid = tid >> 5, lane = tid & 31;
    int base = blockIdx.x * 128;

    if (tid < 128) ((float*)(smem + SATT))[tid] = atts[tid];
    if (tid < 256) ((float*)(smem + SVD))[tid]  = vd[tid];

    for (int i = tid; i < 2048; i += 256) {      // 2048 uint4 per matrix
        int r = i >> 4, c16 = i & 15;
        *(uint4*)(smem + SWH + r * XB_STRIDE + c16 * 16) = ((const uint4*)wh)[i];
        *(uint4*)(smem + SWL + r * XB_STRIDE + c16 * 16) = ((const uint4*)wl)[i];
    }

    {
        const float2* svd2 = (const float2*)(smem + SVD);
        #pragma unroll 1
        for (int k = 0; k < 16; k++) {
            int r = wid + 8 * k;
            int row = base + r;
            float4 xv = make_float4(0.f, 0.f, 0.f, 0.f);
            if (row < NN)
                xv = ((const float4*)(X + (size_t)row * 128))[lane];
            __nv_bfloat162 p0 = __float22bfloat162_rn(make_float2(xv.x, xv.y));
            __nv_bfloat162 p1 = __float22bfloat162_rn(make_float2(xv.z, xv.w));
            uint2 st; st.x = *(unsigned*)&p0; st.y = *(unsigned*)&p1;
            *(uint2*)(smem + SMX + r * XB_STRIDE + lane * 8) = st;
            float2 v0 = svd2[lane * 4 + 0], v1 = svd2[lane * 4 + 1];
            float2 v2 = svd2[lane * 4 + 2], v3 = svd2[lane * 4 + 3];
            float pd0 = xv.x * v0.x + xv.y * v1.x + xv.z * v2.x + xv.w * v3.x;
            float pd1 = xv.x * v0.y + xv.y * v1.y + xv.z * v2.y + xv.w * v3.y;
            #pragma unroll
            for (int o = 16; o; o >>= 1) {
                pd0 += __shfl_xor_sync(0xffffffffu, pd0, o);
                pd1 += __shfl_xor_sync(0xffffffffu, pd1, o);
            }
            if (lane == 0 && row < NN)
                ((float2*)av_d)[row] = make_float2(pd0, pd1);
        }
    }
    __syncthreads();

    float acc[16][4];
    #pragma unroll
    for (int nt = 0; nt < 16; nt++)
        #pragma unroll
        for (int q = 0; q < 4; q++) acc[nt][q] = 0.f;

    int gid = lane >> 2, tig = lane & 3;
    int rowA = wid * 16 + gid;
    const char* sx = smem + SMX;

    #pragma unroll 1
    for (int pass = 0; pass < 2; pass++) {
        const char* sw = smem + (pass ? SWL : SWH);
        #pragma unroll 1
        for (int ks = 0; ks < 8; ks++) {
            int k0 = ks * 16;
            uint32_t a0 = *(const uint32_t*)(sx + rowA * XB_STRIDE + (k0 + 2 * tig) * 2);
            uint32_t a1 = *(const uint32_t*)(sx + (rowA + 8) * XB_STRIDE + (k0 + 2 * tig) * 2);
            uint32_t a2 = *(const uint32_t*)(sx + rowA * XB_STRIDE + (k0 + 8 + 2 * tig) * 2);
            uint32_t a3 = *(const uint32_t*)(sx + (rowA + 8) * XB_STRIDE + (k0 + 8 + 2 * tig) * 2);
            #pragma unroll
            for (int nt = 0; nt < 16; nt++) {
                const char* wr = sw + (nt * 8 + gid) * XB_STRIDE;
                uint32_t b0 = *(const uint32_t*)(wr + (k0 + 2 * tig) * 2);
                uint32_t b1 = *(const uint32_t*)(wr + (k0 + 8 + 2 * tig) * 2);
                mma16816(acc[nt], a0, a1, a2, a3, b0, b1);
            }
        }
    }

    {
        const float* sa = (const float*)(smem + SATT);
        int row0 = base + wid * 16 + gid;
        int row1 = row0 + 8;
        float p0h0 = 0.f, p0h1 = 0.f, p1h0 = 0.f, p1h1 = 0.f;
        #pragma unroll
        for (int nt = 0; nt < 16; nt++) {
            int col = nt * 8 + 2 * tig;
            float s0 = sa[col], s1 = sa[col + 1];
            float d00 = acc[nt][0] * s0 + acc[nt][1] * s1;
            float d01 = acc[nt][2] * s0 + acc[nt][3] * s1;
            if (nt < 8) { p0h0 += d00; p1h0 += d01; }
            else        { p0h1 += d00; p1h1 += d01; }
            __nv_bfloat162 q0 = __float22bfloat162_rn(make_float2(acc[nt][0], acc[nt][1]));
            __nv_bfloat162 q1 = __float22bfloat162_rn(make_float2(acc[nt][2], acc[nt][3]));
            if (row0 < NN) *(unsigned*)(xsb + (size_t)row0 * 128 + col) = *(unsigned*)&q0;
            if (row1 < NN) *(unsigned*)(xsb + (size_t)row1 * 128 + col) = *(unsigned*)&q1;
        }
        #pragma unroll
        for (int o = 1; o <= 2; o <<= 1) {
            p0h0 += __shfl_xor_sync(0xffffffffu, p0h0, o);
            p0h1 += __shfl_xor_sync(0xffffffffu, p0h1, o);
            p1h0 += __shfl_xor_sync(0xffffffffu, p1h0, o);
            p1h1 += __shfl_xor_sync(0xffffffffu, p1h1, o);
        }
        if (tig == 0) {
            if (row0 < NN) ((float2*)av_s)[row0] = make_float2(p0h0, p0h1);
            if (row1 < NN) ((float2*)av_s)[row1] = make_float2(p1h0, p1h1);
        }
    }
}

// ================= fused GAT aggregation: half-warp per edge =================
// Staged weights (32 edges at a time), then two edges in flight per warp:
// lanes 0-15 take even staged edges, 16-31 odd. Each half-warp lane loads
// uint4 (8 cols); halves merged by shfl_xor(16) at the end.
__global__ void __launch_bounds__(256) gat_agg(
        const int* __restrict__ rowptr, const int* __restrict__ col,
        const float* __restrict__ a_s, const float* __restrict__ a_d,
        const __nv_bfloat16* __restrict__ xsb, const float* __restrict__ b,
        float* __restrict__ out)
{
    __shared__ int   ss [8][32];
    __shared__ float sw0[8][32];
    __shared__ float sw1[8][32];
    int wid = threadIdx.x >> 5, lane = threadIdx.x & 31;
    int n = blockIdx.x * 8 + wid;
    if (n >= NN) return;
    int r0 = rowptr[n], r1 = rowptr[n + 1];
    int deg = r1 - r0;
    float2 adv = ((const float2*)a_d)[n];

    int half = lane >> 4;        // which staged-edge parity this lane processes
    int hl   = lane & 15;        // position within half-warp (covers cols hl*8..hl*8+7)
    int h    = hl >> 3;          // head of this lane's columns

    float acc[8];
    #pragma unroll
    for (int q = 0; q < 8; q++) acc[q] = 0.f;
    float ws0 = 0.f, ws1 = 0.f;

    for (int base = 0; base < deg; base += 32) {
        int e = base + lane;
        int s = n; float w0 = 0.f, w1 = 0.f;
        if (e < deg) {
            s = __ldg(col + r0 + e);
            float2 av = ((const float2*)a_s)[s];
            float l0 = av.x + adv.x; l0 = l0 > 0.f ? l0 : 0.2f * l0;
            float l1 = av.y + adv.y; l1 = l1 > 0.f ? l1 : 0.2f * l1;
            w0 = __expf(l0); w1 = __expf(l1);
            ws0 += w0; ws1 += w1;
        }
        ss [wid][lane] = s;
        sw0[wid][lane] = w0;
        sw1[wid][lane] = w1;
        __syncwarp();
        int cnt = min(32, deg - base);
        const float* swh = h ? sw1[wid] : sw0[wid];
        #pragma unroll 4
        for (int e2 = half; e2 < cnt; e2 += 2) {
            int   sj = ss[wid][e2];
            float wj = swh[e2];
            uint4 v = ((const uint4*)(xsb + (size_t)sj * 128))[hl];
            __nv_bfloat162* pv = (__nv_bfloat162*)&v;
            #pragma unroll
            for (int q = 0; q < 4; q++) {
                float2 f = __bfloat1622float2(pv[q]);
                acc[2 * q]     += wj * f.x;
                acc[2 * q + 1] += wj * f.y;
            }
        }
        __syncwarp();
    }

    // merge halves (same columns, different edge subsets)
    #pragma unroll
    for (int q = 0; q < 8; q++)
        acc[q] += __shfl_xor_sync(0xffffffffu, acc[q], 16);

    #pragma unroll
    for (int off = 16; off; off >>= 1) {
        ws0 += __shfl_xor_sync(0xffffffffu, ws0, off);
        ws1 += __shfl_xor_sync(0xffffffffu, ws1, off);
    }
    float inv = 1.f / (h ? ws1 : ws0);

    if (half == 0) {
        float4 b0 = ((const float4*)b)[hl * 2];
        float4 b1 = ((const float4*)b)[hl * 2 + 1];
        float4 o0, o1;
        o0.x = fmaxf(acc[0] * inv + b0.x, 0.f);
        o0.y = fmaxf(acc[1] * inv + b0.y, 0.f);
        o0.z = fmaxf(acc[2] * inv + b0.z, 0.f);
        o0.w = fmaxf(acc[3] * inv + b0.w, 0.f);
        o1.x = fmaxf(acc[4] * inv + b1.x, 0.f);
        o1.y = fmaxf(acc[5] * inv + b1.y, 0.f);
        o1.z = fmaxf(acc[6] * inv + b1.z, 0.f);
        o1.w = fmaxf(acc[7] * inv + b1.w, 0.f);
        ((float4*)(out + (size_t)n * 128))[hl * 2]     = o0;
        ((float4*)(out + (size_t)n * 128))[hl * 2 + 1] = o1;
    }
}

// ================= fused pooling + final linear (batch is SORTED) ============
__global__ void __launch_bounds__(256) pool_final(
        const float* __restrict__ h, const int* __restrict__ batch,
        const float* __restrict__ Wl, const float* __restrict__ bl,
        float* __restrict__ out)
{
    __shared__ float part[256];
    __shared__ float row[128];
    int g = blockIdx.x;

    int a = 0, bnd = NN;
    while (a < bnd) { int m = (a + bnd) >> 1; if (batch[m] < g) a = m + 1; else bnd = m; }
    int lo = a;
    a = lo; bnd = NN;
    while (a < bnd) { int m = (a + bnd) >> 1; if (batch[m] < g + 1) a = m + 1; else bnd = m; }
    int hi = a;

    int c    = threadIdx.x & 127;
    int half = threadIdx.x >> 7;
    float acc = 0.f;
    for (int r = lo + half; r < hi; r += 2)
        acc += h[(size_t)r * 128 + c];
    part[threadIdx.x] = acc;
    __syncthreads();
    if (threadIdx.x < 128) {
        float inv = 1.f / fmaxf((float)(hi - lo), 1.f);
        row[threadIdx.x] = (part[threadIdx.x] + part[threadIdx.x + 128]) * inv;
    }
    __syncthreads();
    if (threadIdx.x < OUTD) {
        float s = bl[threadIdx.x];
        #pragma unroll 16
        for (int j = 0; j < 128; j++)
            s += row[j] * Wl[j * OUTD + threadIdx.x];
        out[g * OUTD + threadIdx.x] = s;
    }
}

// ================= launch =====================================================
extern "C" void kernel_launch(void* const* d_in, const int* in_sizes, int n_in,
                              void* d_out, int out_size)
{
    const float* x     = (const float*)d_in[0];
    const int*   ei    = (const int*)  d_in[1];
    const int*   batch = (const int*)  d_in[2];
    const float* Ws1   = (const float*)d_in[3];
    const float* Wd1   = (const float*)d_in[4];
    const float* as1   = (const float*)d_in[5];
    const float* ad1   = (const float*)d_in[6];
    const float* b1    = (const float*)d_in[7];
    const float* Ws2   = (const float*)d_in[8];
    const float* Wd2   = (const float*)d_in[9];
    const float* as2   = (const float*)d_in[10];
    const float* ad2   = (const float*)d_in[11];
    const float* b2    = (const float*)d_in[12];
    const float* Wl    = (const float*)d_in[13];
    const float* bl    = (const float*)d_in[14];
    float* out = (float*)d_out;

    void *p_xsb, *p_as, *p_ad, *p_h, *p_vd1, *p_vd2;
    void *p_wh1, *p_wl1, *p_wh2, *p_wl2;
    void *p_deg, *p_rowptr, *p_cursor, *p_col, *p_bsum;
    cudaGetSymbolAddress(&p_xsb, g_xsb);
    cudaGetSymbolAddress(&p_as,  g_as);
    cudaGetSymbolAddress(&p_ad,  g_ad);
    cudaGetSymbolAddress(&p_h,   g_h);
    cudaGetSymbolAddress(&p_vd1, g_vd1);
    cudaGetSymbolAddress(&p_vd2, g_vd2);
    cudaGetSymbolAddress(&p_wh1, g_wh1);
    cudaGetSymbolAddress(&p_wl1, g_wl1);
    cudaGetSymbolAddress(&p_wh2, g_wh2);
    cudaGetSymbolAddress(&p_wl2, g_wl2);
    cudaGetSymbolAddress(&p_deg,    g_deg);
    cudaGetSymbolAddress(&p_rowptr, g_rowptr);
    cudaGetSymbolAddress(&p_cursor, g_cursor);
    cudaGetSymbolAddress(&p_col,    g_col);
    cudaGetSymbolAddress(&p_bsum,   g_bsum);

    __nv_bfloat16* xsb = (__nv_bfloat16*)p_xsb;
    float* asv = (float*)p_as;  float* adv = (float*)p_ad;
    float* hbuf= (float*)p_h;
    float* vd1 = (float*)p_vd1; float* vd2 = (float*)p_vd2;
    __nv_bfloat16* wh1 = (__nv_bfloat16*)p_wh1;
    __nv_bfloat16* wl1 = (__nv_bfloat16*)p_wl1;
    __nv_bfloat16* wh2 = (__nv_bfloat16*)p_wh2;
    __nv_bfloat16* wl2 = (__nv_bfloat16*)p_wl2;
    int* deg    = (int*)p_deg;    int* rowptr = (int*)p_rowptr;
    int* cursor = (int*)p_cursor; int* col    = (int*)p_col;
    int* bsum   = (int*)p_bsum;

    const int AGG_GRID  = (NN + 7) / 8;
    const int EDGE_GRID = (ET + 255) / 256;
    const int NODE_GRID = (NN + 255) / 256;

    cudaFuncSetAttribute(proj_tc, cudaFuncAttributeMaxDynamicSharedMemorySize, SM_DYN);

    prelude<<<196, 256>>>(Wd1, ad1, vd1, Wd2, ad2, vd2, deg);
    wprep<<<2, 256>>>(Ws1, Ws2, wh1, wl1, wh2, wl2);

    csr_hist<<<EDGE_GRID, 256>>>(ei, deg);
    scan_block<<<SBLK, 1024>>>(deg, rowptr, bsum);
    scan_sums<<<1, 64>>>(bsum);
    csr_finalize<<<NODE_GRID, 256>>>(bsum, rowptr, cursor);
    csr_fill<<<EDGE_GRID, 256>>>(ei, cursor, col);

    proj_tc<<<NTILE, 256, SM_DYN>>>(x, wh1, wl1, as1, vd1, xsb, asv, adv);
    gat_agg<<<AGG_GRID, 256>>>(rowptr, col, asv, adv, xsb, b1, hbuf);

    proj_tc<<<NTILE, 256, SM_DYN>>>(hbuf, wh2, wl2, as2, vd2, xsb, asv, adv);
    gat_agg<<<AGG_GRID, 256>>>(rowptr, col, asv, adv, xsb, b2, hbuf);

    pool_final<<<GG, 256>>>(hbuf, batch, Wl, bl, out);
}

// round 12
// speedup vs baseline: 4.3911x; 1.0103x over previous
#include <cuda_runtime.h>
#include <cuda_bf16.h>
#include <cstdint>

#define NN   50000
#define EE   800000
#define ET   (EE + NN)        // edges incl. self loops = 850000
#define FD   128
#define HH   2
#define GG   64
#define OUTD 10
#define NTILE ((NN + 127) / 128)   // 391 M-tiles
#define SBLK ((NN + 1023) / 1024)  // 49 scan blocks

// ---------------- scratch (device globals; no allocation allowed) ----------
__device__ alignas(16) __nv_bfloat16 g_xsb[NN * FD];  // bf16 features
__device__ alignas(16) float g_as [NN * HH];     // source attention logits
__device__ alignas(16) float g_ad [NN * HH];     // dest attention logits
__device__ alignas(16) float g_h  [NN * FD];     // layer output (fp32)
__device__ alignas(16) float g_vd1 [FD * HH];    // Wd1 @ ad1
__device__ alignas(16) float g_vd2 [FD * HH];    // Wd2 @ ad2
// W^T bf16 hi/lo (row-major [n][k], 128x128 bf16 = 32KB each)
__device__ alignas(16) __nv_bfloat16 g_wh1[FD * FD];
__device__ alignas(16) __nv_bfloat16 g_wl1[FD * FD];
__device__ alignas(16) __nv_bfloat16 g_wh2[FD * FD];
__device__ alignas(16) __nv_bfloat16 g_wl2[FD * FD];
// CSR
__device__ int g_deg   [NN];
__device__ int g_rowptr[NN + 1];
__device__ int g_cursor[NN];
__device__ int g_col   [ET];
__device__ int g_bsum  [SBLK];

// ================= prelude: zero deg + vd vectors =============================
__global__ void prelude(const float* __restrict__ Wd1, const float* __restrict__ ad1,
                        float* __restrict__ vd1,
                        const float* __restrict__ Wd2, const float* __restrict__ ad2,
                        float* __restrict__ vd2,
                        int* __restrict__ deg)
{
    int i = blockIdx.x * blockDim.x + threadIdx.x;
    for (int j = i; j < NN; j += gridDim.x * blockDim.x) deg[j] = 0;
    if (blockIdx.x < 2 && threadIdx.x < 128) {
        const float* Wd = blockIdx.x ? Wd2 : Wd1;
        const float* ad = blockIdx.x ? ad2 : ad1;
        float*       vd = blockIdx.x ? vd2 : vd1;
        int k = threadIdx.x;
        #pragma unroll
        for (int h = 0; h < HH; h++) {
            float s = 0.f;
            #pragma unroll 16
            for (int c = 0; c < 64; c++)
                s += Wd[k * 128 + h * 64 + c] * ad[h * 64 + c];
            vd[k * 2 + h] = s;
        }
    }
}

// ========== W -> transposed bf16 hi/lo: WT[n][k] = W[k][n], hi + residual ====
__global__ void wprep(const float* __restrict__ W1, const float* __restrict__ W2,
                      __nv_bfloat16* __restrict__ wh1, __nv_bfloat16* __restrict__ wl1,
                      __nv_bfloat16* __restrict__ wh2, __nv_bfloat16* __restrict__ wl2)
{
    const float* W = blockIdx.x ? W2 : W1;
    __nv_bfloat16* wh = blockIdx.x ? wh2 : wh1;
    __nv_bfloat16* wl = blockIdx.x ? wl2 : wl1;
    for (int idx = threadIdx.x; idx < FD * FD; idx += blockDim.x) {
        int n = idx >> 7, k = idx & 127;
        float x = W[k * 128 + n];
        __nv_bfloat16 h = __float2bfloat16_rn(x);
        __nv_bfloat16 l = __float2bfloat16_rn(x - __bfloat162float(h));
        wh[n * 128 + k] = h;
        wl[n * 128 + k] = l;
    }
}

// ================= CSR build ==================================================
__global__ void csr_hist(const int* __restrict__ ei, int* __restrict__ deg) {
    int t = blockIdx.x * blockDim.x + threadIdx.x;
    if (t >= ET) return;
    int d = (t < EE) ? __ldg(ei + EE + t) : (t - EE);
    atomicAdd(&deg[d], 1);
}

__global__ void __launch_bounds__(1024) scan_block(
        const int* __restrict__ deg, int* __restrict__ rowptr, int* __restrict__ bsum)
{
    __shared__ int sh[1024];
    int i = blockIdx.x * 1024 + threadIdx.x;
    int v = (i < NN) ? deg[i] : 0;
    sh[threadIdx.x] = v;
    __syncthreads();
    #pragma unroll
    for (int s = 1; s < 1024; s <<= 1) {
        int t = (threadIdx.x >= s) ? sh[threadIdx.x - s] : 0;
        __syncthreads();
        sh[threadIdx.x] += t;
        __syncthreads();
    }
    if (i < NN) rowptr[i] = sh[threadIdx.x] - v;     // exclusive within block
    if (threadIdx.x == 1023) bsum[blockIdx.x] = sh[1023];
}

__global__ void scan_sums(int* __restrict__ bsum) {
    __shared__ int sh[64];
    int tid = threadIdx.x;
    int v = (tid < SBLK) ? bsum[tid] : 0;
    sh[tid] = v;
    __syncthreads();
    #pragma unroll
    for (int s = 1; s < 64; s <<= 1) {
        int t = (tid >= s) ? sh[tid - s] : 0;
        __syncthreads();
        sh[tid] += t;
        __syncthreads();
    }
    if (tid < SBLK) bsum[tid] = sh[tid] - v;          // exclusive
}

__global__ void csr_finalize(const int* __restrict__ bsum, int* __restrict__ rowptr,
                             int* __restrict__ cursor) {
    int i = blockIdx.x * blockDim.x + threadIdx.x;
    if (i < NN) {
        int v = rowptr[i] + bsum[i >> 10];
        rowptr[i] = v;
        cursor[i] = v;
    }
    if (i == 0) rowptr[NN] = ET;
}

__global__ void csr_fill(const int* __restrict__ ei, int* __restrict__ cursor,
                         int* __restrict__ col) {
    int t = blockIdx.x * blockDim.x + threadIdx.x;
    if (t >= ET) return;
    int s, d;
    if (t < EE) { s = __ldg(ei + t); d = __ldg(ei + EE + t); } else { s = d = t - EE; }
    int pos = atomicAdd(&cursor[d], 1);
    col[pos] = s;
}

// ================= tensor-core projection (mma.sync bf16 HMMA) ===============
#define XB_STRIDE 272                 // bytes per padded smem row (136 bf16)
#define SMX  0
#define SWH  34816
#define SWL  69632
#define SATT 104448                   // 128 f32
#define SVD  104960                   // 256 f32
#define SM_DYN 105984

__device__ __forceinline__ void mma16816(float* c, uint32_t a0, uint32_t a1,
                                         uint32_t a2, uint32_t a3,
                                         uint32_t b0, uint32_t b1) {
    asm volatile(
        "mma.sync.aligned.m16n8k16.row.col.f32.bf16.bf16.f32 "
        "{%0,%1,%2,%3}, {%4,%5,%6,%7}, {%8,%9}, {%0,%1,%2,%3};"
        : "+f"(c[0]), "+f"(c[1]), "+f"(c[2]), "+f"(c[3])
        : "r"(a0), "r"(a1), "r"(a2), "r"(a3), "r"(b0), "r"(b1));
}

__global__ void __launch_bounds__(256)
proj_tc(const float* __restrict__ X,
        const __nv_bfloat16* __restrict__ wh, const __nv_bfloat16* __restrict__ wl,
        const float* __restrict__ atts, const float* __restrict__ vd,
        __nv_bfloat16* __restrict__ xsb,
        float* __restrict__ av_s, float* __restrict__ av_d)
{
    extern __shared__ char smem[];
    int tid = threadIdx.x, wid = tid >> 5, lane = tid & 31;
    int base = blockIdx.x * 128;

    if (tid < 128) ((float*)(smem + SATT))[tid] = atts[tid];
    if (tid < 256) ((float*)(smem + SVD))[tid]  = vd[tid];

    for (int i = tid; i < 2048; i += 256) {      // 2048 uint4 per matrix
        int r = i >> 4, c16 = i & 15;
        *(uint4*)(smem + SWH + r * XB_STRIDE + c16 * 16) = ((const uint4*)wh)[i];
        *(uint4*)(smem + SWL + r * XB_STRIDE + c16 * 16) = ((const uint4*)wl)[i];
    }

    {
        const float2* svd2 = (const float2*)(smem + SVD);
        #pragma unroll 1
        for (int k = 0; k < 16; k++) {
            int r = wid + 8 * k;
            int row = base + r;
            float4 xv = make_float4(0.f, 0.f, 0.f, 0.f);
            if (row < NN)
                xv = ((const float4*)(X + (size_t)row * 128))[lane];
            __nv_bfloat162 p0 = __float22bfloat162_rn(make_float2(xv.x, xv.y));
            __nv_bfloat162 p1 = __float22bfloat162_rn(make_float2(xv.z, xv.w));
            uint2 st; st.x = *(unsigned*)&p0; st.y = *(unsigned*)&p1;
            *(uint2*)(smem + SMX + r * XB_STRIDE + lane * 8) = st;
            float2 v0 = svd2[lane * 4 + 0], v1 = svd2[lane * 4 + 1];
            float2 v2 = svd2[lane * 4 + 2], v3 = svd2[lane * 4 + 3];
            float pd0 = xv.x * v0.x + xv.y * v1.x + xv.z * v2.x + xv.w * v3.x;
            float pd1 = xv.x * v0.y + xv.y * v1.y + xv.z * v2.y + xv.w * v3.y;
            #pragma unroll
            for (int o = 16; o; o >>= 1) {
                pd0 += __shfl_xor_sync(0xffffffffu, pd0, o);
                pd1 += __shfl_xor_sync(0xffffffffu, pd1, o);
            }
            if (lane == 0 && row < NN)
                ((float2*)av_d)[row] = make_float2(pd0, pd1);
        }
    }
    __syncthreads();

    float acc[16][4];
    #pragma unroll
    for (int nt = 0; nt < 16; nt++)
        #pragma unroll
        for (int q = 0; q < 4; q++) acc[nt][q] = 0.f;

    int gid = lane >> 2, tig = lane & 3;
    int rowA = wid * 16 + gid;
    const char* sx = smem + SMX;

    #pragma unroll 1
    for (int pass = 0; pass < 2; pass++) {
        const char* sw = smem + (pass ? SWL : SWH);
        #pragma unroll 1
        for (int ks = 0; ks < 8; ks++) {
            int k0 = ks * 16;
            uint32_t a0 = *(const uint32_t*)(sx + rowA * XB_STRIDE + (k0 + 2 * tig) * 2);
            uint32_t a1 = *(const uint32_t*)(sx + (rowA + 8) * XB_STRIDE + (k0 + 2 * tig) * 2);
            uint32_t a2 = *(const uint32_t*)(sx + rowA * XB_STRIDE + (k0 + 8 + 2 * tig) * 2);
            uint32_t a3 = *(const uint32_t*)(sx + (rowA + 8) * XB_STRIDE + (k0 + 8 + 2 * tig) * 2);
            #pragma unroll
            for (int nt = 0; nt < 16; nt++) {
                const char* wr = sw + (nt * 8 + gid) * XB_STRIDE;
                uint32_t b0 = *(const uint32_t*)(wr + (k0 + 2 * tig) * 2);
                uint32_t b1 = *(const uint32_t*)(wr + (k0 + 8 + 2 * tig) * 2);
                mma16816(acc[nt], a0, a1, a2, a3, b0, b1);
            }
        }
    }

    {
        const float* sa = (const float*)(smem + SATT);
        int row0 = base + wid * 16 + gid;
        int row1 = row0 + 8;
        float p0h0 = 0.f, p0h1 = 0.f, p1h0 = 0.f, p1h1 = 0.f;
        #pragma unroll
        for (int nt = 0; nt < 16; nt++) {
            int col = nt * 8 + 2 * tig;
            float s0 = sa[col], s1 = sa[col + 1];
            float d00 = acc[nt][0] * s0 + acc[nt][1] * s1;
            float d01 = acc[nt][2] * s0 + acc[nt][3] * s1;
            if (nt < 8) { p0h0 += d00; p1h0 += d01; }
            else        { p0h1 += d00; p1h1 += d01; }
            __nv_bfloat162 q0 = __float22bfloat162_rn(make_float2(acc[nt][0], acc[nt][1]));
            __nv_bfloat162 q1 = __float22bfloat162_rn(make_float2(acc[nt][2], acc[nt][3]));
            if (row0 < NN) *(unsigned*)(xsb + (size_t)row0 * 128 + col) = *(unsigned*)&q0;
            if (row1 < NN) *(unsigned*)(xsb + (size_t)row1 * 128 + col) = *(unsigned*)&q1;
        }
        #pragma unroll
        for (int o = 1; o <= 2; o <<= 1) {
            p0h0 += __shfl_xor_sync(0xffffffffu, p0h0, o);
            p0h1 += __shfl_xor_sync(0xffffffffu, p0h1, o);
            p1h0 += __shfl_xor_sync(0xffffffffu, p1h0, o);
            p1h1 += __shfl_xor_sync(0xffffffffu, p1h1, o);
        }
        if (tig == 0) {
            if (row0 < NN) ((float2*)av_s)[row0] = make_float2(p0h0, p0h1);
            if (row1 < NN) ((float2*)av_s)[row1] = make_float2(p1h0, p1h1);
        }
    }
}

// ======= fused GAT aggregation: CONVERGENT shfl staging, half-warp gather ====
// Both half-warps execute identical trip counts (rounds is even), so every
// __shfl_sync is warp-converged. Padded slot (e2 == cnt, cnt odd) stages
// s = n (valid) with w = 0 — contributes exactly zero.
__global__ void __launch_bounds__(256) gat_agg(
        const int* __restrict__ rowptr, const int* __restrict__ col,
        const float* __restrict__ a_s, const float* __restrict__ a_d,
        const __nv_bfloat16* __restrict__ xsb, const float* __restrict__ b,
        float* __restrict__ out)
{
    int wid = threadIdx.x >> 5, lane = threadIdx.x & 31;
    int n = blockIdx.x * 8 + wid;
    if (n >= NN) return;
    int r0 = rowptr[n], r1 = rowptr[n + 1];
    int deg = r1 - r0;
    float2 adv = ((const float2*)a_d)[n];

    int half = lane >> 4;        // staged-edge parity this lane gathers
    int hl   = lane & 15;        // covers cols hl*8 .. hl*8+7
    int h    = hl >> 3;          // head of this lane's columns

    float acc[8];
    #pragma unroll
    for (int q = 0; q < 8; q++) acc[q] = 0.f;
    float ws0 = 0.f, ws1 = 0.f;

    for (int base = 0; base < deg; base += 32) {
        int e = base + lane;
        int s = n; float w0 = 0.f, w1 = 0.f;
        if (e < deg) {
            s = __ldg(col + r0 + e);
            float2 av = ((const float2*)a_s)[s];
            float l0 = av.x + adv.x; l0 = l0 > 0.f ? l0 : 0.2f * l0;
            float l1 = av.y + adv.y; l1 = l1 > 0.f ? l1 : 0.2f * l1;
            w0 = __expf(l0); w1 = __expf(l1);
            ws0 += w0; ws1 += w1;
        }
        int cnt = min(32, deg - base);
        int rounds = (cnt + 1) & ~1;           // even: both halves same trips
        #pragma unroll 4
        for (int e2 = half; e2 < rounds; e2 += 2) {
            int   sj  = __shfl_sync(0xffffffffu, s,  e2);
            float w0j = __shfl_sync(0xffffffffu, w0, e2);
            float w1j = __shfl_sync(0xffffffffu, w1, e2);
            float wj  = h ? w1j : w0j;
            uint4 v = ((const uint4*)(xsb + (size_t)sj * 128))[hl];
            __nv_bfloat162* pv = (__nv_bfloat162*)&v;
            #pragma unroll
            for (int q = 0; q < 4; q++) {
                float2 f = __bfloat1622float2(pv[q]);
                acc[2 * q]     += wj * f.x;
                acc[2 * q + 1] += wj * f.y;
            }
        }
    }

    // merge halves (same columns, different edge subsets)
    #pragma unroll
    for (int q = 0; q < 8; q++)
        acc[q] += __shfl_xor_sync(0xffffffffu, acc[q], 16);

    #pragma unroll
    for (int off = 16; off; off >>= 1) {
        ws0 += __shfl_xor_sync(0xffffffffu, ws0, off);
        ws1 += __shfl_xor_sync(0xffffffffu, ws1, off);
    }
    float inv = 1.f / (h ? ws1 : ws0);

    if (half == 0) {
        float4 b0 = ((const float4*)b)[hl * 2];
        float4 b1 = ((const float4*)b)[hl * 2 + 1];
        float4 o0, o1;
        o0.x = fmaxf(acc[0] * inv + b0.x, 0.f);
        o0.y = fmaxf(acc[1] * inv + b0.y, 0.f);
        o0.z = fmaxf(acc[2] * inv + b0.z, 0.f);
        o0.w = fmaxf(acc[3] * inv + b0.w, 0.f);
        o1.x = fmaxf(acc[4] * inv + b1.x, 0.f);
        o1.y = fmaxf(acc[5] * inv + b1.y, 0.f);
        o1.z = fmaxf(acc[6] * inv + b1.z, 0.f);
        o1.w = fmaxf(acc[7] * inv + b1.w, 0.f);
        ((float4*)(out + (size_t)n * 128))[hl * 2]     = o0;
        ((float4*)(out + (size_t)n * 128))[hl * 2 + 1] = o1;
    }
}

// ================= fused pooling + final linear (batch is SORTED) ============
__global__ void __launch_bounds__(256) pool_final(
        const float* __restrict__ h, const int* __restrict__ batch,
        const float* __restrict__ Wl, const float* __restrict__ bl,
        float* __restrict__ out)
{
    __shared__ float part[256];
    __shared__ float row[128];
    int g = blockIdx.x;

    int a = 0, bnd = NN;
    while (a < bnd) { int m = (a + bnd) >> 1; if (batch[m] < g) a = m + 1; else bnd = m; }
    int lo = a;
    a = lo; bnd = NN;
    while (a < bnd) { int m = (a + bnd) >> 1; if (batch[m] < g + 1) a = m + 1; else bnd = m; }
    int hi = a;

    int c    = threadIdx.x & 127;
    int half = threadIdx.x >> 7;
    float acc = 0.f;
    for (int r = lo + half; r < hi; r += 2)
        acc += h[(size_t)r * 128 + c];
    part[threadIdx.x] = acc;
    __syncthreads();
    if (threadIdx.x < 128) {
        float inv = 1.f / fmaxf((float)(hi - lo), 1.f);
        row[threadIdx.x] = (part[threadIdx.x] + part[threadIdx.x + 128]) * inv;
    }
    __syncthreads();
    if (threadIdx.x < OUTD) {
        float s = bl[threadIdx.x];
        #pragma unroll 16
        for (int j = 0; j < 128; j++)
            s += row[j] * Wl[j * OUTD + threadIdx.x];
        out[g * OUTD + threadIdx.x] = s;
    }
}

// ================= launch =====================================================
extern "C" void kernel_launch(void* const* d_in, const int* in_sizes, int n_in,
                              void* d_out, int out_size)
{
    const float* x     = (const float*)d_in[0];
    const int*   ei    = (const int*)  d_in[1];
    const int*   batch = (const int*)  d_in[2];
    const float* Ws1   = (const float*)d_in[3];
    const float* Wd1   = (const float*)d_in[4];
    const float* as1   = (const float*)d_in[5];
    const float* ad1   = (const float*)d_in[6];
    const float* b1    = (const float*)d_in[7];
    const float* Ws2   = (const float*)d_in[8];
    const float* Wd2   = (const float*)d_in[9];
    const float* as2   = (const float*)d_in[10];
    const float* ad2   = (const float*)d_in[11];
    const float* b2    = (const float*)d_in[12];
    const float* Wl    = (const float*)d_in[13];
    const float* bl    = (const float*)d_in[14];
    float* out = (float*)d_out;

    void *p_xsb, *p_as, *p_ad, *p_h, *p_vd1, *p_vd2;
    void *p_wh1, *p_wl1, *p_wh2, *p_wl2;
    void *p_deg, *p_rowptr, *p_cursor, *p_col, *p_bsum;
    cudaGetSymbolAddress(&p_xsb, g_xsb);
    cudaGetSymbolAddress(&p_as,  g_as);
    cudaGetSymbolAddress(&p_ad,  g_ad);
    cudaGetSymbolAddress(&p_h,   g_h);
    cudaGetSymbolAddress(&p_vd1, g_vd1);
    cudaGetSymbolAddress(&p_vd2, g_vd2);
    cudaGetSymbolAddress(&p_wh1, g_wh1);
    cudaGetSymbolAddress(&p_wl1, g_wl1);
    cudaGetSymbolAddress(&p_wh2, g_wh2);
    cudaGetSymbolAddress(&p_wl2, g_wl2);
    cudaGetSymbolAddress(&p_deg,    g_deg);
    cudaGetSymbolAddress(&p_rowptr, g_rowptr);
    cudaGetSymbolAddress(&p_cursor, g_cursor);
    cudaGetSymbolAddress(&p_col,    g_col);
    cudaGetSymbolAddress(&p_bsum,   g_bsum);

    __nv_bfloat16* xsb = (__nv_bfloat16*)p_xsb;
    float* asv = (float*)p_as;  float* adv = (float*)p_ad;
    float* hbuf= (float*)p_h;
    float* vd1 = (float*)p_vd1; float* vd2 = (float*)p_vd2;
    __nv_bfloat16* wh1 = (__nv_bfloat16*)p_wh1;
    __nv_bfloat16* wl1 = (__nv_bfloat16*)p_wl1;
    __nv_bfloat16* wh2 = (__nv_bfloat16*)p_wh2;
    __nv_bfloat16* wl2 = (__nv_bfloat16*)p_wl2;
    int* deg    = (int*)p_deg;    int* rowptr = (int*)p_rowptr;
    int* cursor = (int*)p_cursor; int* col    = (int*)p_col;
    int* bsum   = (int*)p_bsum;

    const int AGG_GRID  = (NN + 7) / 8;
    const int EDGE_GRID = (ET + 255) / 256;
    const int NODE_GRID = (NN + 255) / 256;

    cudaFuncSetAttribute(proj_tc, cudaFuncAttributeMaxDynamicSharedMemorySize, SM_DYN);

    prelude<<<196, 256>>>(Wd1, ad1, vd1, Wd2, ad2, vd2, deg);
    wprep<<<2, 256>>>(Ws1, Ws2, wh1, wl1, wh2, wl2);

    csr_hist<<<EDGE_GRID, 256>>>(ei, deg);
    scan_block<<<SBLK, 1024>>>(deg, rowptr, bsum);
    scan_sums<<<1, 64>>>(bsum);
    csr_finalize<<<NODE_GRID, 256>>>(bsum, rowptr, cursor);
    csr_fill<<<EDGE_GRID, 256>>>(ei, cursor, col);

    proj_tc<<<NTILE, 256, SM_DYN>>>(x, wh1, wl1, as1, vd1, xsb, asv, adv);
    gat_agg<<<AGG_GRID, 256>>>(rowptr, col, asv, adv, xsb, b1, hbuf);

    proj_tc<<<NTILE, 256, SM_DYN>>>(hbuf, wh2, wl2, as2, vd2, xsb, asv, adv);
    gat_agg<<<AGG_GRID, 256>>>(rowptr, col, asv, adv, xsb, b2, hbuf);

    pool_final<<<GG, 256>>>(hbuf, batch, Wl, bl, out);
}

// round 13
// speedup vs baseline: 4.6199x; 1.0521x over previous
#include <cuda_runtime.h>
#include <cuda_bf16.h>
#include <cstdint>

#define NN   50000
#define EE   800000
#define ET   (EE + NN)        // edges incl. self loops = 850000
#define FD   128
#define HH   2
#define GG   64
#define OUTD 10
#define NTILE ((NN + 127) / 128)   // 391 M-tiles
#define SBLK ((NN + 1023) / 1024)  // 49 scan blocks
#define PUBF (1 << 30)             // publish flag bit

// ---------------- scratch (device globals; no allocation allowed) ----------
__device__ alignas(16) __nv_bfloat16 g_xsb[NN * FD];  // bf16 features
__device__ alignas(16) float g_as [NN * HH];
__device__ alignas(16) float g_ad [NN * HH];
__device__ alignas(16) float g_h  [NN * FD];
__device__ alignas(16) float g_vd1 [FD * HH];
__device__ alignas(16) float g_vd2 [FD * HH];
__device__ alignas(16) __nv_bfloat16 g_wh1[FD * FD];
__device__ alignas(16) __nv_bfloat16 g_wl1[FD * FD];
__device__ alignas(16) __nv_bfloat16 g_wh2[FD * FD];
__device__ alignas(16) __nv_bfloat16 g_wl2[FD * FD];
// CSR
__device__ int g_deg   [NN];
__device__ int g_rowptr[NN + 1];
__device__ int g_cursor[NN];
__device__ int g_col   [ET];
__device__ int g_pub   [SBLK];

// ====== prep: deg=1 (self loop), pub=0, vd vectors, W transposed hi/lo ======
__global__ void prep(const float* __restrict__ Wd1, const float* __restrict__ ad1,
                     float* __restrict__ vd1,
                     const float* __restrict__ Wd2, const float* __restrict__ ad2,
                     float* __restrict__ vd2,
                     const float* __restrict__ Ws1, const float* __restrict__ Ws2,
                     __nv_bfloat16* __restrict__ wh1, __nv_bfloat16* __restrict__ wl1,
                     __nv_bfloat16* __restrict__ wh2, __nv_bfloat16* __restrict__ wl2,
                     int* __restrict__ deg, int* __restrict__ pub)
{
    int b = blockIdx.x, t = threadIdx.x;
    int i = b * 256 + t;
    if (i < NN) deg[i] = 1;                       // self loop pre-counted
    if (i < SBLK) pub[i] = 0;                     // scan publish slots

    if (b < 128) {
        const float* W = (b < 64) ? Ws1 : Ws2;
        __nv_bfloat16* wh = (b < 64) ? wh1 : wh2;
        __nv_bfloat16* wl = (b < 64) ? wl1 : wl2;
        int idx = (b & 63) * 256 + t;             // 0..16383
        int n = idx >> 7, k = idx & 127;
        float x = W[k * 128 + n];
        __nv_bfloat16 h = __float2bfloat16_rn(x);
        __nv_bfloat16 l = __float2bfloat16_rn(x - __bfloat162float(h));
        wh[n * 128 + k] = h;
        wl[n * 128 + k] = l;
    } else if (b < 130 && t < 128) {
        const float* Wd = (b == 129) ? Wd2 : Wd1;
        const float* ad = (b == 129) ? ad2 : ad1;
        float*       vd = (b == 129) ? vd2 : vd1;
        int k = t;
        #pragma unroll
        for (int h = 0; h < HH; h++) {
            float s = 0.f;
            #pragma unroll 16
            for (int c = 0; c < 64; c++)
                s += Wd[k * 128 + h * 64 + c] * ad[h * 64 + c];
            vd[k * 2 + h] = s;
        }
    }
}

// ======= CSR hist: 4 edges per thread (scalar loads on harness ptr) =========
__global__ void csr_hist(const int* __restrict__ ei, int* __restrict__ deg) {
    int t = blockIdx.x * blockDim.x + threadIdx.x;   // t < EE/4
    if (t >= EE / 4) return;
    int d0 = __ldg(ei + EE + 4 * t + 0);
    int d1 = __ldg(ei + EE + 4 * t + 1);
    int d2 = __ldg(ei + EE + 4 * t + 2);
    int d3 = __ldg(ei + EE + 4 * t + 3);
    atomicAdd(&deg[d0], 1);
    atomicAdd(&deg[d1], 1);
    atomicAdd(&deg[d2], 1);
    atomicAdd(&deg[d3], 1);
}

// ======= fused scan: publish block aggregate, spin on predecessors ==========
// 49 blocks <= 148 SMs -> all co-resident; value-carrying atomics need no fence.
__global__ void __launch_bounds__(1024) scan_fused(
        const int* __restrict__ deg, int* __restrict__ rowptr,
        int* __restrict__ cursor, int* __restrict__ pub)
{
    __shared__ int sh[1024];
    __shared__ int s_prefix;
    int b = blockIdx.x, t = threadIdx.x;
    int i = b * 1024 + t;
    int v = (i < NN) ? deg[i] : 0;
    sh[t] = v;
    if (t == 0) s_prefix = 0;
    __syncthreads();
    #pragma unroll
    for (int s = 1; s < 1024; s <<= 1) {
        int tmp = (t >= s) ? sh[t - s] : 0;
        __syncthreads();
        sh[t] += tmp;
        __syncthreads();
    }
    if (t == 1023) atomicExch(&pub[b], sh[1023] + PUBF);   // publish aggregate
    // gather predecessor prefix (lane-parallel spin over <= 48 entries)
    if (t < 64 && t < b) {
        int acc = 0;
        for (int p = t; p < b; p += 64) {
            int x;
            do { x = atomicAdd(&pub[p], 0); } while (x < PUBF);
            acc += x - PUBF;
        }
        atomicAdd(&s_prefix, acc);
    }
    __syncthreads();
    int base = s_prefix;
    if (i < NN) {
        int r = base + sh[t] - v;       // exclusive scan + block prefix
        rowptr[i] = r;
        cursor[i] = r + 1;              // slot 0 reserved for self loop
    }
    if (b == 0 && t == 0) rowptr[NN] = ET;
}

// fill: threads [0, EE/4) scatter real edges (4 each); [EE/4, EE/4+NN) self loops
__global__ void csr_fill(const int* __restrict__ ei, const int* __restrict__ rowptr,
                         int* __restrict__ cursor, int* __restrict__ col) {
    int t = blockIdx.x * blockDim.x + threadIdx.x;
    if (t < EE / 4) {
        #pragma unroll
        for (int j = 0; j < 4; j++) {
            int s = __ldg(ei + 4 * t + j);
            int d = __ldg(ei + EE + 4 * t + j);
            col[atomicAdd(&cursor[d], 1)] = s;
        }
    } else if (t < EE / 4 + NN) {
        int n = t - EE / 4;
        col[rowptr[n]] = n;             // self loop at slot 0
    }
}

// ================= tensor-core projection (mma.sync bf16 HMMA) ===============
#define XB_STRIDE 272                 // bytes per padded smem row (136 bf16)
#define SMX  0
#define SWH  34816
#define SWL  69632
#define SATT 104448                   // 128 f32
#define SVD  104960                   // 256 f32
#define SM_DYN 105984

__device__ __forceinline__ void mma16816(float* c, uint32_t a0, uint32_t a1,
                                         uint32_t a2, uint32_t a3,
                                         uint32_t b0, uint32_t b1) {
    asm volatile(
        "mma.sync.aligned.m16n8k16.row.col.f32.bf16.bf16.f32 "
        "{%0,%1,%2,%3}, {%4,%5,%6,%7}, {%8,%9}, {%0,%1,%2,%3};"
        : "+f"(c[0]), "+f"(c[1]), "+f"(c[2]), "+f"(c[3])
        : "r"(a0), "r"(a1), "r"(a2), "r"(a3), "r"(b0), "r"(b1));
}

__global__ void __launch_bounds__(256)
proj_tc(const float* __restrict__ X,
        const __nv_bfloat16* __restrict__ wh, const __nv_bfloat16* __restrict__ wl,
        const float* __restrict__ atts, const float* __restrict__ vd,
        __nv_bfloat16* __restrict__ xsb,
        float* __restrict__ av_s, float* __restrict__ av_d)
{
    extern __shared__ char smem[];
    int tid = threadIdx.x, wid = tid >> 5, lane = tid & 31;
    int base = blockIdx.x * 128;

    if (tid < 128) ((float*)(smem + SATT))[tid] = atts[tid];
    if (tid < 256) ((float*)(smem + SVD))[tid]  = vd[tid];

    for (int i = tid; i < 2048; i += 256) {      // 2048 uint4 per matrix
        int r = i >> 4, c16 = i & 15;
        *(uint4*)(smem + SWH + r * XB_STRIDE + c16 * 16) = ((const uint4*)wh)[i];
        *(uint4*)(smem + SWL + r * XB_STRIDE + c16 * 16) = ((const uint4*)wl)[i];
    }

    {
        const float2* svd2 = (const float2*)(smem + SVD);
        #pragma unroll 1
        for (int k = 0; k < 16; k++) {
            int r = wid + 8 * k;
            int row = base + r;
            float4 xv = make_float4(0.f, 0.f, 0.f, 0.f);
            if (row < NN)
                xv = ((const float4*)(X + (size_t)row * 128))[lane];
            __nv_bfloat162 p0 = __float22bfloat162_rn(make_float2(xv.x, xv.y));
            __nv_bfloat162 p1 = __float22bfloat162_rn(make_float2(xv.z, xv.w));
            uint2 st; st.x = *(unsigned*)&p0; st.y = *(unsigned*)&p1;
            *(uint2*)(smem + SMX + r * XB_STRIDE + lane * 8) = st;
            float2 v0 = svd2[lane * 4 + 0], v1 = svd2[lane * 4 + 1];
            float2 v2 = svd2[lane * 4 + 2], v3 = svd2[lane * 4 + 3];
            float pd0 = xv.x * v0.x + xv.y * v1.x + xv.z * v2.x + xv.w * v3.x;
            float pd1 = xv.x * v0.y + xv.y * v1.y + xv.z * v2.y + xv.w * v3.y;
            #pragma unroll
            for (int o = 16; o; o >>= 1) {
                pd0 += __shfl_xor_sync(0xffffffffu, pd0, o);
                pd1 += __shfl_xor_sync(0xffffffffu, pd1, o);
            }
            if (lane == 0 && row < NN)
                ((float2*)av_d)[row] = make_float2(pd0, pd1);
        }
    }
    __syncthreads();

    float acc[16][4];
    #pragma unroll
    for (int nt = 0; nt < 16; nt++)
        #pragma unroll
        for (int q = 0; q < 4; q++) acc[nt][q] = 0.f;

    int gid = lane >> 2, tig = lane & 3;
    int rowA = wid * 16 + gid;
    const char* sx = smem + SMX;

    #pragma unroll 1
    for (int pass = 0; pass < 2; pass++) {
        const char* sw = smem + (pass ? SWL : SWH);
        #pragma unroll 1
        for (int ks = 0; ks < 8; ks++) {
            int k0 = ks * 16;
            uint32_t a0 = *(const uint32_t*)(sx + rowA * XB_STRIDE + (k0 + 2 * tig) * 2);
            uint32_t a1 = *(const uint32_t*)(sx + (rowA + 8) * XB_STRIDE + (k0 + 2 * tig) * 2);
            uint32_t a2 = *(const uint32_t*)(sx + rowA * XB_STRIDE + (k0 + 8 + 2 * tig) * 2);
            uint32_t a3 = *(const uint32_t*)(sx + (rowA + 8) * XB_STRIDE + (k0 + 8 + 2 * tig) * 2);
            #pragma unroll
            for (int nt = 0; nt < 16; nt++) {
                const char* wr = sw + (nt * 8 + gid) * XB_STRIDE;
                uint32_t b0 = *(const uint32_t*)(wr + (k0 + 2 * tig) * 2);
                uint32_t b1 = *(const uint32_t*)(wr + (k0 + 8 + 2 * tig) * 2);
                mma16816(acc[nt], a0, a1, a2, a3, b0, b1);
            }
        }
    }

    {
        const float* sa = (const float*)(smem + SATT);
        int row0 = base + wid * 16 + gid;
        int row1 = row0 + 8;
        float p0h0 = 0.f, p0h1 = 0.f, p1h0 = 0.f, p1h1 = 0.f;
        #pragma unroll
        for (int nt = 0; nt < 16; nt++) {
            int col = nt * 8 + 2 * tig;
            float s0 = sa[col], s1 = sa[col + 1];
            float d00 = acc[nt][0] * s0 + acc[nt][1] * s1;
            float d01 = acc[nt][2] * s0 + acc[nt][3] * s1;
            if (nt < 8) { p0h0 += d00; p1h0 += d01; }
            else        { p0h1 += d00; p1h1 += d01; }
            __nv_bfloat162 q0 = __float22bfloat162_rn(make_float2(acc[nt][0], acc[nt][1]));
            __nv_bfloat162 q1 = __float22bfloat162_rn(make_float2(acc[nt][2], acc[nt][3]));
            if (row0 < NN) *(unsigned*)(xsb + (size_t)row0 * 128 + col) = *(unsigned*)&q0;
            if (row1 < NN) *(unsigned*)(xsb + (size_t)row1 * 128 + col) = *(unsigned*)&q1;
        }
        #pragma unroll
        for (int o = 1; o <= 2; o <<= 1) {
            p0h0 += __shfl_xor_sync(0xffffffffu, p0h0, o);
            p0h1 += __shfl_xor_sync(0xffffffffu, p0h1, o);
            p1h0 += __shfl_xor_sync(0xffffffffu, p1h0, o);
            p1h1 += __shfl_xor_sync(0xffffffffu, p1h1, o);
        }
        if (tig == 0) {
            if (row0 < NN) ((float2*)av_s)[row0] = make_float2(p0h0, p0h1);
            if (row1 < NN) ((float2*)av_s)[row1] = make_float2(p1h0, p1h1);
        }
    }
}

// ======= fused GAT aggregation: CONVERGENT shfl staging, half-warp gather ====
__global__ void __launch_bounds__(256) gat_agg(
        const int* __restrict__ rowptr, const int* __restrict__ col,
        const float* __restrict__ a_s, const float* __restrict__ a_d,
        const __nv_bfloat16* __restrict__ xsb, const float* __restrict__ b,
        float* __restrict__ out)
{
    int wid = threadIdx.x >> 5, lane = threadIdx.x & 31;
    int n = blockIdx.x * 8 + wid;
    if (n >= NN) return;
    int r0 = rowptr[n], r1 = rowptr[n + 1];
    int deg = r1 - r0;
    float2 adv = ((const float2*)a_d)[n];

    int half = lane >> 4;
    int hl   = lane & 15;
    int h    = hl >> 3;

    float acc[8];
    #pragma unroll
    for (int q = 0; q < 8; q++) acc[q] = 0.f;
    float ws0 = 0.f, ws1 = 0.f;

    for (int base = 0; base < deg; base += 32) {
        int e = base + lane;
        int s = n; float w0 = 0.f, w1 = 0.f;
        if (e < deg) {
            s = __ldg(col + r0 + e);
            float2 av = ((const float2*)a_s)[s];
            float l0 = av.x + adv.x; l0 = l0 > 0.f ? l0 : 0.2f * l0;
            float l1 = av.y + adv.y; l1 = l1 > 0.f ? l1 : 0.2f * l1;
            w0 = __expf(l0); w1 = __expf(l1);
            ws0 += w0; ws1 += w1;
        }
        int cnt = min(32, deg - base);
        int rounds = (cnt + 1) & ~1;           // even: both halves same trips
        #pragma unroll 4
        for (int e2 = half; e2 < rounds; e2 += 2) {
            int   sj  = __shfl_sync(0xffffffffu, s,  e2);
            float w0j = __shfl_sync(0xffffffffu, w0, e2);
            float w1j = __shfl_sync(0xffffffffu, w1, e2);
            float wj  = h ? w1j : w0j;
            uint4 v = ((const uint4*)(xsb + (size_t)sj * 128))[hl];
            __nv_bfloat162* pv = (__nv_bfloat162*)&v;
            #pragma unroll
            for (int q = 0; q < 4; q++) {
                float2 f = __bfloat1622float2(pv[q]);
                acc[2 * q]     += wj * f.x;
                acc[2 * q + 1] += wj * f.y;
            }
        }
    }

    #pragma unroll
    for (int q = 0; q < 8; q++)
        acc[q] += __shfl_xor_sync(0xffffffffu, acc[q], 16);

    #pragma unroll
    for (int off = 16; off; off >>= 1) {
        ws0 += __shfl_xor_sync(0xffffffffu, ws0, off);
        ws1 += __shfl_xor_sync(0xffffffffu, ws1, off);
    }
    float inv = 1.f / (h ? ws1 : ws0);

    if (half == 0) {
        float4 b0 = ((const float4*)b)[hl * 2];
        float4 b1 = ((const float4*)b)[hl * 2 + 1];
        float4 o0, o1;
        o0.x = fmaxf(acc[0] * inv + b0.x, 0.f);
        o0.y = fmaxf(acc[1] * inv + b0.y, 0.f);
        o0.z = fmaxf(acc[2] * inv + b0.z, 0.f);
        o0.w = fmaxf(acc[3] * inv + b0.w, 0.f);
        o1.x = fmaxf(acc[4] * inv + b1.x, 0.f);
        o1.y = fmaxf(acc[5] * inv + b1.y, 0.f);
        o1.z = fmaxf(acc[6] * inv + b1.z, 0.f);
        o1.w = fmaxf(acc[7] * inv + b1.w, 0.f);
        ((float4*)(out + (size_t)n * 128))[hl * 2]     = o0;
        ((float4*)(out + (size_t)n * 128))[hl * 2 + 1] = o1;
    }
}

// ================= fused pooling + final linear (batch is SORTED) ============
__global__ void __launch_bounds__(256) pool_final(
        const float* __restrict__ h, const int* __restrict__ batch,
        const float* __restrict__ Wl, const float* __restrict__ bl,
        float* __restrict__ out)
{
    __shared__ float part[256];
    __shared__ float row[128];
    int g = blockIdx.x;

    int a = 0, bnd = NN;
    while (a < bnd) { int m = (a + bnd) >> 1; if (batch[m] < g) a = m + 1; else bnd = m; }
    int lo = a;
    a = lo; bnd = NN;
    while (a < bnd) { int m = (a + bnd) >> 1; if (batch[m] < g + 1) a = m + 1; else bnd = m; }
    int hi = a;

    int c    = threadIdx.x & 127;
    int half = threadIdx.x >> 7;
    float acc = 0.f;
    for (int r = lo + half; r < hi; r += 2)
        acc += h[(size_t)r * 128 + c];
    part[threadIdx.x] = acc;
    __syncthreads();
    if (threadIdx.x < 128) {
        float inv = 1.f / fmaxf((float)(hi - lo), 1.f);
        row[threadIdx.x] = (part[threadIdx.x] + part[threadIdx.x + 128]) * inv;
    }
    __syncthreads();
    if (threadIdx.x < OUTD) {
        float s = bl[threadIdx.x];
        #pragma unroll 16
        for (int j = 0; j < 128; j++)
            s += row[j] * Wl[j * OUTD + threadIdx.x];
        out[g * OUTD + threadIdx.x] = s;
    }
}

// ================= launch =====================================================
extern "C" void kernel_launch(void* const* d_in, const int* in_sizes, int n_in,
                              void* d_out, int out_size)
{
    const float* x     = (const float*)d_in[0];
    const int*   ei    = (const int*)  d_in[1];
    const int*   batch = (const int*)  d_in[2];
    const float* Ws1   = (const float*)d_in[3];
    const float* Wd1   = (const float*)d_in[4];
    const float* as1   = (const float*)d_in[5];
    const float* ad1   = (const float*)d_in[6];
    const float* b1    = (const float*)d_in[7];
    const float* Ws2   = (const float*)d_in[8];
    const float* Wd2   = (const float*)d_in[9];
    const float* as2   = (const float*)d_in[10];
    const float* ad2   = (const float*)d_in[11];
    const float* b2    = (const float*)d_in[12];
    const float* Wl    = (const float*)d_in[13];
    const float* bl    = (const float*)d_in[14];
    float* out = (float*)d_out;

    void *p_xsb, *p_as, *p_ad, *p_h, *p_vd1, *p_vd2;
    void *p_wh1, *p_wl1, *p_wh2, *p_wl2;
    void *p_deg, *p_rowptr, *p_cursor, *p_col, *p_pub;
    cudaGetSymbolAddress(&p_xsb, g_xsb);
    cudaGetSymbolAddress(&p_as,  g_as);
    cudaGetSymbolAddress(&p_ad,  g_ad);
    cudaGetSymbolAddress(&p_h,   g_h);
    cudaGetSymbolAddress(&p_vd1, g_vd1);
    cudaGetSymbolAddress(&p_vd2, g_vd2);
    cudaGetSymbolAddress(&p_wh1, g_wh1);
    cudaGetSymbolAddress(&p_wl1, g_wl1);
    cudaGetSymbolAddress(&p_wh2, g_wh2);
    cudaGetSymbolAddress(&p_wl2, g_wl2);
    cudaGetSymbolAddress(&p_deg,    g_deg);
    cudaGetSymbolAddress(&p_rowptr, g_rowptr);
    cudaGetSymbolAddress(&p_cursor, g_cursor);
    cudaGetSymbolAddress(&p_col,    g_col);
    cudaGetSymbolAddress(&p_pub,    g_pub);

    __nv_bfloat16* xsb = (__nv_bfloat16*)p_xsb;
    float* asv = (float*)p_as;  float* adv = (float*)p_ad;
    float* hbuf= (float*)p_h;
    float* vd1 = (float*)p_vd1; float* vd2 = (float*)p_vd2;
    __nv_bfloat16* wh1 = (__nv_bfloat16*)p_wh1;
    __nv_bfloat16* wl1 = (__nv_bfloat16*)p_wl1;
    __nv_bfloat16* wh2 = (__nv_bfloat16*)p_wh2;
    __nv_bfloat16* wl2 = (__nv_bfloat16*)p_wl2;
    int* deg    = (int*)p_deg;    int* rowptr = (int*)p_rowptr;
    int* cursor = (int*)p_cursor; int* col    = (int*)p_col;
    int* pub    = (int*)p_pub;

    const int AGG_GRID  = (NN + 7) / 8;
    const int NODE_GRID = (NN + 255) / 256;
    const int HIST_GRID = (EE / 4 + 255) / 256;
    const int FILL_GRID = (EE / 4 + NN + 255) / 256;

    cudaFuncSetAttribute(proj_tc, cudaFuncAttributeMaxDynamicSharedMemorySize, SM_DYN);

    prep<<<NODE_GRID, 256>>>(Wd1, ad1, vd1, Wd2, ad2, vd2,
                             Ws1, Ws2, wh1, wl1, wh2, wl2, deg, pub);

    csr_hist<<<HIST_GRID, 256>>>(ei, deg);
    scan_fused<<<SBLK, 1024>>>(deg, rowptr, cursor, pub);
    csr_fill<<<FILL_GRID, 256>>>(ei, rowptr, cursor, col);

    proj_tc<<<NTILE, 256, SM_DYN>>>(x, wh1, wl1, as1, vd1, xsb, asv, adv);
    gat_agg<<<AGG_GRID, 256>>>(rowptr, col, asv, adv, xsb, b1, hbuf);

    proj_tc<<<NTILE, 256, SM_DYN>>>(hbuf, wh2, wl2, as2, vd2, xsb, asv, adv);
    gat_agg<<<AGG_GRID, 256>>>(rowptr, col, asv, adv, xsb, b2, hbuf);

    pool_final<<<GG, 256>>>(hbuf, batch, Wl, bl, out);
}